// round 1
// baseline (speedup 1.0000x reference)
#include <cuda_runtime.h>
#include <stdint.h>

#define BB 16
#define MM 1024
#define CC 128
#define BM (BB*MM)
#define NBLK_STATS 2048

#define TI 64
#define TJ 128

// ---------------- device scratch (no allocations allowed) ----------------
__device__ float g_n1[BM];
__device__ float g_n2[BM];
__device__ int g_idx1[BM];
__device__ unsigned long long g_idx2p[BM];
__device__ float g_part[3][NBLK_STATS];

// sortable encoding of float: order-preserving map to uint32
__device__ __forceinline__ unsigned int fenc(float f) {
    unsigned int u = __float_as_uint(f);
    return (u & 0x80000000u) ? ~u : (u | 0x80000000u);
}

// ---------------- K0: init argmin scratch ----------------
__global__ void k_init() {
    int t = blockIdx.x * blockDim.x + threadIdx.x;
    if (t < BM) g_idx2p[t] = 0xFFFFFFFFFFFFFFFFULL;
}

// ---------------- K1: squared norms of every token ----------------
__global__ void __launch_bounds__(128) k_norms(const float* __restrict__ e1,
                                               const float* __restrict__ e2) {
    int t = blockIdx.x * blockDim.x + threadIdx.x; // 0..16383 -> (b, i)
    int b = t >> 10, i = t & 1023;
    const float* p1 = e1 + (size_t)b * CC * MM + i;
    const float* p2 = e2 + (size_t)b * CC * MM + i;
    float s1 = 0.f, s2 = 0.f;
#pragma unroll 8
    for (int c = 0; c < CC; c++) {
        float v = p1[c * MM]; s1 += v * v;
        float w = p2[c * MM]; s2 += w * w;
    }
    g_n1[t] = s1;
    g_n2[t] = s2;
}

// ---------------- K2: fused distance GEMM + dual argmin ----------------
// block: (batch b, i-tile of 64). Loops all j-tiles of 128.
// thread (ty,tx): 4 i's x 8 j's register tile.
__global__ void __launch_bounds__(256) k_argmin(const float* __restrict__ e1,
                                                const float* __restrict__ e2) {
    extern __shared__ float sm[];
    float* As = sm;            // [CC][TI]  c-major
    float* Bs = sm + CC * TI;  // [CC][TJ]
    int b = blockIdx.x;
    int i0 = blockIdx.y * TI;
    int tid = threadIdx.x;
    int ty = tid >> 4, tx = tid & 15;
    const float* base1 = e1 + (size_t)b * CC * MM;
    const float* base2 = e2 + (size_t)b * CC * MM;

    // load A tile once: As[c][ii] = emb1[b][c][i0+ii]
    for (int t = tid; t < CC * TI / 4; t += 256) {
        int c = t >> 4, q = t & 15;
        ((float4*)As)[t] = *(const float4*)(base1 + (size_t)c * MM + i0 + q * 4);
    }

    float n1r[4];
    int ib = i0 + ty * 4;
#pragma unroll
    for (int u = 0; u < 4; u++) n1r[u] = g_n1[b * MM + ib + u];

    unsigned long long run1[4];
#pragma unroll
    for (int u = 0; u < 4; u++) run1[u] = 0xFFFFFFFFFFFFFFFFULL;

    for (int j0 = 0; j0 < MM; j0 += TJ) {
        __syncthreads();
        for (int t = tid; t < CC * TJ / 4; t += 256) {
            int c = t >> 5, q = t & 31;
            ((float4*)Bs)[t] = *(const float4*)(base2 + (size_t)c * MM + j0 + q * 4);
        }
        __syncthreads();

        float acc[4][8];
#pragma unroll
        for (int u = 0; u < 4; u++)
#pragma unroll
            for (int v = 0; v < 8; v++) acc[u][v] = 0.f;

#pragma unroll 4
        for (int c = 0; c < CC; c++) {
            float4 af = ((float4*)As)[c * 16 + ty];
            float4 b0 = ((float4*)Bs)[c * 32 + tx * 2];
            float4 b1 = ((float4*)Bs)[c * 32 + tx * 2 + 1];
            float a[4] = {af.x, af.y, af.z, af.w};
            float bv[8] = {b0.x, b0.y, b0.z, b0.w, b1.x, b1.y, b1.z, b1.w};
#pragma unroll
            for (int u = 0; u < 4; u++)
#pragma unroll
                for (int v = 0; v < 8; v++) acc[u][v] += a[u] * bv[v];
        }

        int jb = j0 + tx * 8;
        float n2r[8];
#pragma unroll
        for (int v = 0; v < 8; v++) n2r[v] = g_n2[b * MM + jb + v];

        // idx1: running min over j for each of my 4 i's
#pragma unroll
        for (int u = 0; u < 4; u++) {
#pragma unroll
            for (int v = 0; v < 8; v++) {
                float val = fmaf(-2.f, acc[u][v], n2r[v]);
                unsigned long long pk =
                    ((unsigned long long)fenc(val) << 32) | (unsigned)(jb + v);
                if (pk < run1[u]) run1[u] = pk;
            }
        }
        // idx2: local min over my 4 i's for each of my 8 j's, then global atomicMin
#pragma unroll
        for (int v = 0; v < 8; v++) {
            unsigned long long mn = 0xFFFFFFFFFFFFFFFFULL;
#pragma unroll
            for (int u = 0; u < 4; u++) {
                float val = fmaf(-2.f, acc[u][v], n1r[u]);
                unsigned long long pk =
                    ((unsigned long long)fenc(val) << 32) | (unsigned)(ib + u);
                if (pk < mn) mn = pk;
            }
            atomicMin(&g_idx2p[b * MM + jb + v], mn);
        }
    }

    // reduce run1 across the 16 tx lanes (half-warp groups), lane tx==0 writes
#pragma unroll
    for (int u = 0; u < 4; u++) {
        unsigned long long r = run1[u];
#pragma unroll
        for (int off = 8; off >= 1; off >>= 1) {
            unsigned long long o = __shfl_down_sync(0xFFFFFFFFu, r, off, 16);
            if (o < r) r = o;
        }
        if (tx == 0) g_idx1[b * MM + ib + u] = (int)(r & 0xFFFFFFFFu);
    }
}

// ---------------- K3: gather NN + vicreg statistics per position ----------------
// block: (position i, pair p). p=0: x=m1, y=nn1(m2 gathered by idx1)
//                              p=1: x=m2, y=nn2(m1 gathered by idx2)
// threads: 128 (one per channel c).
__global__ void __launch_bounds__(128) k_stats(const float* __restrict__ e1,
                                               const float* __restrict__ e2) {
    __shared__ __align__(16) float Xs[2][16][132];
    __shared__ float sred[12];
    int i = blockIdx.x;
    int p = blockIdx.y;
    int c = threadIdx.x;
    const float* xs = p ? e2 : e1;
    const float* ys = p ? e1 : e2;

    float x[16], y[16];
#pragma unroll
    for (int b = 0; b < 16; b++) {
        int j;
        if (p == 0) j = g_idx1[b * MM + i];
        else        j = (int)(g_idx2p[b * MM + i] & 0xFFFFFFFFULL);
        x[b] = xs[(size_t)b * CC * MM + (size_t)c * MM + i];
        y[b] = ys[(size_t)b * CC * MM + (size_t)c * MM + j];
    }

    // invariance term (uncentered)
    float repr = 0.f;
#pragma unroll
    for (int b = 0; b < 16; b++) { float d = x[b] - y[b]; repr += d * d; }

    // center over batch
    float mux = 0.f, muy = 0.f;
#pragma unroll
    for (int b = 0; b < 16; b++) { mux += x[b]; muy += y[b]; }
    mux *= (1.f / 16.f); muy *= (1.f / 16.f);

    float sx = 0.f, sy = 0.f;
#pragma unroll
    for (int b = 0; b < 16; b++) {
        x[b] -= mux; sx += x[b] * x[b];
        y[b] -= muy; sy += y[b] * y[b];
    }
    float stdp = fmaxf(0.f, 1.f - sqrtf(sx * (1.f / 15.f) + 1e-4f))
               + fmaxf(0.f, 1.f - sqrtf(sy * (1.f / 15.f) + 1e-4f));
    float S2 = sx * sx + sy * sy;   // per-c contribution to sum of diag^2 (x225)

    // stash centered vectors for the Gram computation
#pragma unroll
    for (int b = 0; b < 16; b++) {
        Xs[0][b][c] = x[b];
        Xs[1][b][c] = y[b];
    }
    __syncthreads();

    // ||G||_F^2 via 136 symmetric pair-dots per tensor (272 dots over 128 threads)
    float covpart = -S2;
    for (int d = c; d < 272; d += 128) {
        int tpr = (d >= 136) ? 1 : 0;
        int pr = d - tpr * 136;
        int a = 0, rem = pr;
        while (rem >= 16 - a) { rem -= 16 - a; a++; }
        int b2 = a + rem;
        const float4* ra = (const float4*)&Xs[tpr][a][0];
        const float4* rb = (const float4*)&Xs[tpr][b2][0];
        float g = 0.f;
#pragma unroll
        for (int q = 0; q < 32; q++) {
            float4 va = ra[q], vb = rb[q];
            g += va.x * vb.x + va.y * vb.y + va.z * vb.z + va.w * vb.w;
        }
        float w = (a == b2) ? 1.f : 2.f;
        covpart += w * g * g;
    }

    // block-reduce three scalars, write deterministic per-block partials
    float v0 = repr, v1 = stdp, v2 = covpart;
#pragma unroll
    for (int off = 16; off >= 1; off >>= 1) {
        v0 += __shfl_down_sync(0xFFFFFFFFu, v0, off);
        v1 += __shfl_down_sync(0xFFFFFFFFu, v1, off);
        v2 += __shfl_down_sync(0xFFFFFFFFu, v2, off);
    }
    int w = c >> 5;
    if ((c & 31) == 0) { sred[w] = v0; sred[4 + w] = v1; sred[8 + w] = v2; }
    __syncthreads();
    if (c == 0) {
        int blk = p * 1024 + i;
        g_part[0][blk] = sred[0] + sred[1] + sred[2] + sred[3];
        g_part[1][blk] = sred[4] + sred[5] + sred[6] + sred[7];
        g_part[2][blk] = sred[8] + sred[9] + sred[10] + sred[11];
    }
}

// ---------------- K4: deterministic final reduction + scaling ----------------
__global__ void __launch_bounds__(1024) k_final(float* __restrict__ out) {
    __shared__ float sred[32];
    int t = threadIdx.x;
    for (int s = 0; s < 3; s++) {
        float v = g_part[s][t] + g_part[s][t + 1024];
#pragma unroll
        for (int off = 16; off >= 1; off >>= 1)
            v += __shfl_down_sync(0xFFFFFFFFu, v, off);
        if ((t & 31) == 0) sred[t >> 5] = v;
        __syncthreads();
        if (t == 0) {
            float tot = 0.f;
            for (int w2 = 0; w2 < 32; w2++) tot += sred[w2];
            float scale;
            if (s == 0)      scale = 25.f / (2.f * 2097152.f);   // inv
            else if (s == 1) scale = 25.f / (4.f * 131072.f);    // var
            else             scale = 1.f / (225.f * 524288.f);   // cov
            out[s] = tot * scale;
        }
        __syncthreads();
    }
}

// ---------------- launch ----------------
extern "C" void kernel_launch(void* const* d_in, const int* in_sizes, int n_in,
                              void* d_out, int out_size) {
    const float* e1 = (const float*)d_in[0];
    const float* e2 = (const float*)d_in[1];
    float* out = (float*)d_out;

    (void)in_sizes; (void)n_in; (void)out_size;

    int smem = (CC * TI + CC * TJ) * 4;  // 98304 bytes
    cudaFuncSetAttribute(k_argmin, cudaFuncAttributeMaxDynamicSharedMemorySize, smem);

    k_init<<<BM / 256, 256>>>();
    k_norms<<<BM / 128, 128>>>(e1, e2);
    k_argmin<<<dim3(BB, MM / TI), 256, smem>>>(e1, e2);
    k_stats<<<dim3(MM, 2), 128>>>(e1, e2);
    k_final<<<1, 1024>>>(out);
}

// round 3
// speedup vs baseline: 2.5677x; 2.5677x over previous
#include <cuda_runtime.h>
#include <cuda_bf16.h>
#include <stdint.h>

#define BB 16
#define MM 1024
#define CC 128
#define BM (BB*MM)

// ---------------- device scratch ----------------
__device__ float g_n1[BM];
__device__ float g_n2[BM];
__device__ unsigned long long g_idx1p[BM];
__device__ unsigned long long g_idx2p[BM];
__device__ float g_part[3][2048];
__device__ float g_t1[(size_t)BM * CC];   // t1[b][i][c] fp32
__device__ float g_t2[(size_t)BM * CC];

// ---------------- helpers ----------------
__device__ __forceinline__ uint32_t smem_u32(const void* p) {
    uint32_t a;
    asm("{ .reg .u64 t; cvta.to.shared.u64 t, %1; cvt.u32.u64 %0, t; }" : "=r"(a) : "l"(p));
    return a;
}
__device__ __forceinline__ unsigned int fenc(float f) {
    unsigned int u = __float_as_uint(f);
    return (u & 0x80000000u) ? ~u : (u | 0x80000000u);
}
__device__ __forceinline__ uint32_t pk2(__nv_bfloat16 a, __nv_bfloat16 b) {
    return (uint32_t)__bfloat16_as_ushort(a) | ((uint32_t)__bfloat16_as_ushort(b) << 16);
}

#define LDMX4(r0, r1, r2, r3, addr) \
    asm volatile("ldmatrix.sync.aligned.m8n8.x4.shared.b16 {%0,%1,%2,%3}, [%4];" \
        : "=r"(r0), "=r"(r1), "=r"(r2), "=r"(r3) : "r"(addr))

#define MMA16816(d, a0, a1, a2, a3, b0, b1) \
    asm volatile("mma.sync.aligned.m16n8k16.row.col.f32.bf16.bf16.f32 " \
        "{%0,%1,%2,%3}, {%4,%5,%6,%7}, {%8,%9}, {%0,%1,%2,%3};" \
        : "+f"((d)[0]), "+f"((d)[1]), "+f"((d)[2]), "+f"((d)[3]) \
        : "r"(a0), "r"(a1), "r"(a2), "r"(a3), "r"(b0), "r"(b1))

// ---------------- K0: init ----------------
__global__ void k_init() {
    int t = blockIdx.x * blockDim.x + threadIdx.x;
    if (t < BM) { g_idx1p[t] = ~0ULL; g_idx2p[t] = ~0ULL; }
}

// ---------------- K1: transpose (b,c,i) -> (b,i,c) ----------------
__global__ void __launch_bounds__(256) k_trans(const float* __restrict__ e1,
                                               const float* __restrict__ e2) {
    __shared__ float sm[2][32][33];
    int b = blockIdx.z;
    int i0 = blockIdx.x * 32, c0 = blockIdx.y * 32;
    int tx = threadIdx.x, ty = threadIdx.y;
    const float* s1 = e1 + (size_t)b * CC * MM;
    const float* s2 = e2 + (size_t)b * CC * MM;
#pragma unroll
    for (int q = 0; q < 4; q++) {
        int c = c0 + ty + q * 8;
        sm[0][ty + q * 8][tx] = s1[(size_t)c * MM + i0 + tx];
        sm[1][ty + q * 8][tx] = s2[(size_t)c * MM + i0 + tx];
    }
    __syncthreads();
#pragma unroll
    for (int q = 0; q < 4; q++) {
        int i = i0 + ty + q * 8;
        g_t1[((size_t)b * MM + i) * CC + c0 + tx] = sm[0][tx][ty + q * 8];
        g_t2[((size_t)b * MM + i) * CC + c0 + tx] = sm[1][tx][ty + q * 8];
    }
}

// ---------------- K2: squared norms ----------------
__global__ void __launch_bounds__(128) k_norms(const float* __restrict__ e1,
                                               const float* __restrict__ e2) {
    int t = blockIdx.x * blockDim.x + threadIdx.x;
    int b = t >> 10, i = t & 1023;
    const float* p1 = e1 + (size_t)b * CC * MM + i;
    const float* p2 = e2 + (size_t)b * CC * MM + i;
    float s1 = 0.f, s2 = 0.f;
#pragma unroll 8
    for (int c = 0; c < CC; c++) {
        float v = p1[c * MM]; s1 += v * v;
        float w = p2[c * MM]; s2 += w * w;
    }
    g_n1[t] = s1;
    g_n2[t] = s2;
}

// ---------------- K3: mma.sync bf16-split GEMM + dual argmin ----------------
// K=384 split: seg0 A=hi B=hi, seg1 A=hi B=lo, seg2 A=lo B=hi (drops lo*lo).
// Block tile 128(i) x 128(j) per iter; 8 j-iters. 8 warps: warp tile 64x32.
#define STR 784           // bytes per smem row: 392 halves (384 + 8 pad)
#define SMEM_DOTS (256 * STR)

__global__ void __launch_bounds__(256, 1) k_dots() {
    extern __shared__ char smem[];
    uint32_t sb = smem_u32(smem);
    uint32_t SA = sb, SB = sb + 128 * STR;
    int tid = threadIdx.x, wid = tid >> 5, l = tid & 31;
    int b = blockIdx.y;
    int i0 = blockIdx.x * 128;
    const float* At = g_t1 + ((size_t)b * MM + i0) * CC;
    const float* Bt = g_t2 + (size_t)b * MM * CC;

    int m0w = (wid >> 2) * 64;
    int n0w = (wid & 3) * 32;

    // ---- load + convert A tile (done once) ----
#pragma unroll
    for (int q = 0; q < 16; q++) {
        int t = tid + q * 256;
        int i = t >> 5, c4 = (t & 31) * 4;
        float4 v = *(const float4*)(At + (size_t)i * CC + c4);
        __nv_bfloat16 hx = __float2bfloat16(v.x), hy = __float2bfloat16(v.y);
        __nv_bfloat16 hz = __float2bfloat16(v.z), hw = __float2bfloat16(v.w);
        uint32_t h0 = pk2(hx, hy), h1 = pk2(hz, hw);
        uint32_t l0 = pk2(__float2bfloat16(v.x - __bfloat162float(hx)),
                          __float2bfloat16(v.y - __bfloat162float(hy)));
        uint32_t l1 = pk2(__float2bfloat16(v.z - __bfloat162float(hz)),
                          __float2bfloat16(v.w - __bfloat162float(hw)));
        char* row = smem + (size_t)i * STR;
        *(uint32_t*)(row + c4 * 2)             = h0;
        *(uint32_t*)(row + c4 * 2 + 4)         = h1;
        *(uint32_t*)(row + (128 + c4) * 2)     = h0;   // seg1: A = hi
        *(uint32_t*)(row + (128 + c4) * 2 + 4) = h1;
        *(uint32_t*)(row + (256 + c4) * 2)     = l0;   // seg2: A = lo
        *(uint32_t*)(row + (256 + c4) * 2 + 4) = l1;
    }

    // per-lane invariant ldmatrix offsets
    int rowA = (l & 7) + ((l >> 3) & 1) * 8;
    int koffA = (l >> 4) * 8;
    uint32_t aBase = SA + (uint32_t)(m0w + rowA) * STR + koffA * 2;
    int rowB = (l & 7) + ((l >> 4) & 1) * 8;
    int koffB = ((l >> 3) & 1) * 8;
    uint32_t bBase = SB + (uint32_t)(n0w + rowB) * STR + koffB * 2;

    float n1r[4][2];
#pragma unroll
    for (int mf = 0; mf < 4; mf++)
#pragma unroll
        for (int h = 0; h < 2; h++)
            n1r[mf][h] = g_n1[b * MM + i0 + m0w + mf * 16 + (l >> 2) + h * 8];

    unsigned long long run1[4][2];
#pragma unroll
    for (int mf = 0; mf < 4; mf++) { run1[mf][0] = ~0ULL; run1[mf][1] = ~0ULL; }

#pragma unroll 1
    for (int jt = 0; jt < 8; jt++) {
        int j0 = jt * 128;
        __syncthreads();
        // ---- load + convert B tile ----
#pragma unroll
        for (int q = 0; q < 16; q++) {
            int t = tid + q * 256;
            int j = t >> 5, c4 = (t & 31) * 4;
            float4 v = *(const float4*)(Bt + (size_t)(j0 + j) * CC + c4);
            __nv_bfloat16 hx = __float2bfloat16(v.x), hy = __float2bfloat16(v.y);
            __nv_bfloat16 hz = __float2bfloat16(v.z), hw = __float2bfloat16(v.w);
            uint32_t h0 = pk2(hx, hy), h1 = pk2(hz, hw);
            uint32_t l0 = pk2(__float2bfloat16(v.x - __bfloat162float(hx)),
                              __float2bfloat16(v.y - __bfloat162float(hy)));
            uint32_t l1 = pk2(__float2bfloat16(v.z - __bfloat162float(hz)),
                              __float2bfloat16(v.w - __bfloat162float(hw)));
            char* row = smem + 128 * STR + (size_t)j * STR;
            *(uint32_t*)(row + c4 * 2)             = h0;
            *(uint32_t*)(row + c4 * 2 + 4)         = h1;
            *(uint32_t*)(row + (128 + c4) * 2)     = l0;   // seg1: B = lo
            *(uint32_t*)(row + (128 + c4) * 2 + 4) = l1;
            *(uint32_t*)(row + (256 + c4) * 2)     = h0;   // seg2: B = hi
            *(uint32_t*)(row + (256 + c4) * 2 + 4) = h1;
        }
        __syncthreads();

        float acc[4][4][4];
#pragma unroll
        for (int mf = 0; mf < 4; mf++)
#pragma unroll
            for (int nf = 0; nf < 4; nf++)
#pragma unroll
                for (int r = 0; r < 4; r++) acc[mf][nf][r] = 0.f;

#pragma unroll 2
        for (int ks = 0; ks < 24; ks++) {
            uint32_t a[4][4];
#pragma unroll
            for (int mf = 0; mf < 4; mf++)
                LDMX4(a[mf][0], a[mf][1], a[mf][2], a[mf][3],
                      aBase + (uint32_t)mf * 16 * STR + ks * 32);
#pragma unroll
            for (int np = 0; np < 2; np++) {
                uint32_t bf0, bf1, bf2, bf3;
                LDMX4(bf0, bf1, bf2, bf3,
                      bBase + (uint32_t)np * 16 * STR + ks * 32);
#pragma unroll
                for (int mf = 0; mf < 4; mf++) {
                    MMA16816(acc[mf][np * 2],     a[mf][0], a[mf][1], a[mf][2], a[mf][3], bf0, bf1);
                    MMA16816(acc[mf][np * 2 + 1], a[mf][0], a[mf][1], a[mf][2], a[mf][3], bf2, bf3);
                }
            }
        }

        // ---- epilogue: dual argmin over this 128x128 tile ----
        float n2r[4][2];
#pragma unroll
        for (int nf = 0; nf < 4; nf++)
#pragma unroll
            for (int p = 0; p < 2; p++)
                n2r[nf][p] = g_n2[b * MM + j0 + n0w + nf * 8 + (l & 3) * 2 + p];

        // row minima (idx1): min over this warp's 32 cols
#pragma unroll
        for (int mf = 0; mf < 4; mf++)
#pragma unroll
            for (int h = 0; h < 2; h++) {
                unsigned long long pk = ~0ULL;
#pragma unroll
                for (int nf = 0; nf < 4; nf++)
#pragma unroll
                    for (int p = 0; p < 2; p++) {
                        float val = fmaf(-2.f, acc[mf][nf][h * 2 + p], n2r[nf][p]);
                        int j = j0 + n0w + nf * 8 + (l & 3) * 2 + p;
                        unsigned long long e =
                            ((unsigned long long)fenc(val) << 32) | (unsigned)j;
                        if (e < pk) pk = e;
                    }
                unsigned long long o;
                o = __shfl_xor_sync(0xFFFFFFFFu, pk, 1); if (o < pk) pk = o;
                o = __shfl_xor_sync(0xFFFFFFFFu, pk, 2); if (o < pk) pk = o;
                if (pk < run1[mf][h]) run1[mf][h] = pk;
            }

        // col minima (idx2): min over this warp's 64 rows
#pragma unroll
        for (int nf = 0; nf < 4; nf++)
#pragma unroll
            for (int p = 0; p < 2; p++) {
                unsigned long long pk = ~0ULL;
#pragma unroll
                for (int mf = 0; mf < 4; mf++)
#pragma unroll
                    for (int h = 0; h < 2; h++) {
                        float val = fmaf(-2.f, acc[mf][nf][h * 2 + p], n1r[mf][h]);
                        int i = i0 + m0w + mf * 16 + (l >> 2) + h * 8;
                        unsigned long long e =
                            ((unsigned long long)fenc(val) << 32) | (unsigned)i;
                        if (e < pk) pk = e;
                    }
                unsigned long long o;
                o = __shfl_xor_sync(0xFFFFFFFFu, pk, 4);  if (o < pk) pk = o;
                o = __shfl_xor_sync(0xFFFFFFFFu, pk, 8);  if (o < pk) pk = o;
                o = __shfl_xor_sync(0xFFFFFFFFu, pk, 16); if (o < pk) pk = o;
                if (l < 4)
                    atomicMin(&g_idx2p[b * MM + j0 + n0w + nf * 8 + (l & 3) * 2 + p], pk);
            }
    }

    // flush row minima
#pragma unroll
    for (int mf = 0; mf < 4; mf++)
#pragma unroll
        for (int h = 0; h < 2; h++)
            if ((l & 3) == 0)
                atomicMin(&g_idx1p[b * MM + i0 + m0w + mf * 16 + (l >> 2) + h * 8],
                          run1[mf][h]);
}

// ---------------- K4: gather NN + vicreg statistics (coalesced) ----------------
__global__ void __launch_bounds__(128) k_stats() {
    __shared__ __align__(16) float Xs[2][16][132];
    __shared__ float sred[12];
    int i = blockIdx.x;
    int p = blockIdx.y;
    int c = threadIdx.x;
    const float* tx_ = p ? g_t2 : g_t1;
    const float* ty_ = p ? g_t1 : g_t2;

    float x[16], y[16];
#pragma unroll
    for (int b = 0; b < 16; b++) {
        int j = (int)((p ? g_idx2p[b * MM + i] : g_idx1p[b * MM + i]) & 0xFFFFFFFFULL);
        x[b] = tx_[((size_t)b * MM + i) * CC + c];
        y[b] = ty_[((size_t)b * MM + j) * CC + c];
    }

    float repr = 0.f;
#pragma unroll
    for (int b = 0; b < 16; b++) { float d = x[b] - y[b]; repr += d * d; }

    float mux = 0.f, muy = 0.f;
#pragma unroll
    for (int b = 0; b < 16; b++) { mux += x[b]; muy += y[b]; }
    mux *= (1.f / 16.f); muy *= (1.f / 16.f);

    float sx = 0.f, sy = 0.f;
#pragma unroll
    for (int b = 0; b < 16; b++) {
        x[b] -= mux; sx += x[b] * x[b];
        y[b] -= muy; sy += y[b] * y[b];
    }
    float stdp = fmaxf(0.f, 1.f - sqrtf(sx * (1.f / 15.f) + 1e-4f))
               + fmaxf(0.f, 1.f - sqrtf(sy * (1.f / 15.f) + 1e-4f));
    float S2 = sx * sx + sy * sy;

#pragma unroll
    for (int b = 0; b < 16; b++) {
        Xs[0][b][c] = x[b];
        Xs[1][b][c] = y[b];
    }
    __syncthreads();

    float covpart = -S2;
    for (int d = c; d < 272; d += 128) {
        int tpr = (d >= 136) ? 1 : 0;
        int pr = d - tpr * 136;
        int a = 0, rem = pr;
        while (rem >= 16 - a) { rem -= 16 - a; a++; }
        int b2 = a + rem;
        const float4* ra = (const float4*)&Xs[tpr][a][0];
        const float4* rb = (const float4*)&Xs[tpr][b2][0];
        float g = 0.f;
#pragma unroll
        for (int q = 0; q < 32; q++) {
            float4 va = ra[q], vb = rb[q];
            g += va.x * vb.x + va.y * vb.y + va.z * vb.z + va.w * vb.w;
        }
        float w = (a == b2) ? 1.f : 2.f;
        covpart += w * g * g;
    }

    float v0 = repr, v1 = stdp, v2 = covpart;
#pragma unroll
    for (int off = 16; off >= 1; off >>= 1) {
        v0 += __shfl_down_sync(0xFFFFFFFFu, v0, off);
        v1 += __shfl_down_sync(0xFFFFFFFFu, v1, off);
        v2 += __shfl_down_sync(0xFFFFFFFFu, v2, off);
    }
    int w = c >> 5;
    if ((c & 31) == 0) { sred[w] = v0; sred[4 + w] = v1; sred[8 + w] = v2; }
    __syncthreads();
    if (c == 0) {
        int blk = p * 1024 + i;
        g_part[0][blk] = sred[0] + sred[1] + sred[2] + sred[3];
        g_part[1][blk] = sred[4] + sred[5] + sred[6] + sred[7];
        g_part[2][blk] = sred[8] + sred[9] + sred[10] + sred[11];
    }
}

// ---------------- K5: final reduction + scaling ----------------
__global__ void __launch_bounds__(1024) k_final(float* __restrict__ out) {
    __shared__ float sred[32];
    int t = threadIdx.x;
    for (int s = 0; s < 3; s++) {
        float v = g_part[s][t] + g_part[s][t + 1024];
#pragma unroll
        for (int off = 16; off >= 1; off >>= 1)
            v += __shfl_down_sync(0xFFFFFFFFu, v, off);
        if ((t & 31) == 0) sred[t >> 5] = v;
        __syncthreads();
        if (t == 0) {
            float tot = 0.f;
            for (int w2 = 0; w2 < 32; w2++) tot += sred[w2];
            float scale;
            if (s == 0)      scale = 25.f / (2.f * 2097152.f);
            else if (s == 1) scale = 25.f / (4.f * 131072.f);
            else             scale = 1.f / (225.f * 524288.f);
            out[s] = tot * scale;
        }
        __syncthreads();
    }
}

// ---------------- launch ----------------
extern "C" void kernel_launch(void* const* d_in, const int* in_sizes, int n_in,
                              void* d_out, int out_size) {
    const float* e1 = (const float*)d_in[0];
    const float* e2 = (const float*)d_in[1];
    float* out = (float*)d_out;
    (void)in_sizes; (void)n_in; (void)out_size;

    cudaFuncSetAttribute(k_dots, cudaFuncAttributeMaxDynamicSharedMemorySize, SMEM_DOTS);

    k_init<<<BM / 256, 256>>>();
    k_trans<<<dim3(32, 4, 16), dim3(32, 8)>>>(e1, e2);
    k_norms<<<BM / 128, 128>>>(e1, e2);
    k_dots<<<dim3(8, 16), 256, SMEM_DOTS>>>();
    k_stats<<<dim3(MM, 2), 128>>>();
    k_final<<<1, 1024>>>(out);
}

// round 4
// speedup vs baseline: 2.6887x; 1.0471x over previous
#include <cuda_runtime.h>
#include <cuda_bf16.h>
#include <stdint.h>

#define BB 16
#define MM 1024
#define CC 128
#define BM (BB*MM)

// ---------------- device scratch ----------------
__device__ float g_n1[BM];
__device__ float g_n2[BM];
__device__ unsigned long long g_idx1p[BM];
__device__ unsigned long long g_idx2p[BM];
__device__ float g_part[3][2048];
__device__ float g_t1[(size_t)BM * CC];        // fp32 (b,i,c)
__device__ float g_t2[(size_t)BM * CC];
__device__ unsigned short g_hl1[(size_t)BM * 256];  // rows [hi(128)|lo(128)] bf16
__device__ unsigned short g_hl2[(size_t)BM * 256];

// ---------------- helpers ----------------
__device__ __forceinline__ uint32_t smem_u32(const void* p) {
    uint32_t a;
    asm("{ .reg .u64 t; cvta.to.shared.u64 t, %1; cvt.u32.u64 %0, t; }" : "=r"(a) : "l"(p));
    return a;
}
__device__ __forceinline__ unsigned int fenc(float f) {
    unsigned int u = __float_as_uint(f);
    return (u & 0x80000000u) ? ~u : (u | 0x80000000u);
}
__device__ __forceinline__ void cpa16(uint32_t dst, const void* src) {
    asm volatile("cp.async.cg.shared.global [%0], [%1], 16;" :: "r"(dst), "l"(src));
}
#define CP_COMMIT() asm volatile("cp.async.commit_group;" ::: "memory")
#define CP_WAIT(n)  asm volatile("cp.async.wait_group %0;" :: "n"(n) : "memory")

#define LDMX4(r0, r1, r2, r3, addr) \
    asm volatile("ldmatrix.sync.aligned.m8n8.x4.shared.b16 {%0,%1,%2,%3}, [%4];" \
        : "=r"(r0), "=r"(r1), "=r"(r2), "=r"(r3) : "r"(addr))

#define MMA16816(d, a0, a1, a2, a3, b0, b1) \
    asm volatile("mma.sync.aligned.m16n8k16.row.col.f32.bf16.bf16.f32 " \
        "{%0,%1,%2,%3}, {%4,%5,%6,%7}, {%8,%9}, {%0,%1,%2,%3};" \
        : "+f"((d)[0]), "+f"((d)[1]), "+f"((d)[2]), "+f"((d)[3]) \
        : "r"(a0), "r"(a1), "r"(a2), "r"(a3), "r"(b0), "r"(b1))

// ---------------- K1: fused transpose + bf16 hi/lo + idx init ----------------
__global__ void __launch_bounds__(256) k_prep(const float* __restrict__ e1,
                                              const float* __restrict__ e2) {
    __shared__ float sm[2][32][33];
    int b = blockIdx.z;
    int i0 = blockIdx.x * 32, c0 = blockIdx.y * 32;
    int tx = threadIdx.x, ty = threadIdx.y;
    const float* s1 = e1 + (size_t)b * CC * MM;
    const float* s2 = e2 + (size_t)b * CC * MM;
#pragma unroll
    for (int q = 0; q < 4; q++) {
        int c = c0 + ty + q * 8;
        sm[0][ty + q * 8][tx] = s1[(size_t)c * MM + i0 + tx];
        sm[1][ty + q * 8][tx] = s2[(size_t)c * MM + i0 + tx];
    }
    if (blockIdx.y == 0 && ty == 0) {
        g_idx1p[b * MM + i0 + tx] = ~0ULL;
        g_idx2p[b * MM + i0 + tx] = ~0ULL;
    }
    __syncthreads();
#pragma unroll
    for (int q = 0; q < 4; q++) {
        int i = i0 + ty + q * 8;
        size_t row = (size_t)b * MM + i;
        float v1 = sm[0][tx][ty + q * 8];
        float v2 = sm[1][tx][ty + q * 8];
        g_t1[row * CC + c0 + tx] = v1;
        g_t2[row * CC + c0 + tx] = v2;
        __nv_bfloat16 h1 = __float2bfloat16(v1);
        __nv_bfloat16 h2 = __float2bfloat16(v2);
        g_hl1[row * 256 + c0 + tx]       = __bfloat16_as_ushort(h1);
        g_hl1[row * 256 + 128 + c0 + tx] = __bfloat16_as_ushort(__float2bfloat16(v1 - __bfloat162float(h1)));
        g_hl2[row * 256 + c0 + tx]       = __bfloat16_as_ushort(h2);
        g_hl2[row * 256 + 128 + c0 + tx] = __bfloat16_as_ushort(__float2bfloat16(v2 - __bfloat162float(h2)));
    }
}

// ---------------- K2: squared norms (coalesced, one warp per row) ----------------
__global__ void __launch_bounds__(256) k_norms() {
    int row = blockIdx.x * 8 + (threadIdx.x >> 5);
    int l = threadIdx.x & 31;
    const float4* r1 = (const float4*)(g_t1 + (size_t)row * CC);
    const float4* r2 = (const float4*)(g_t2 + (size_t)row * CC);
    float4 v = r1[l];
    float s1 = v.x * v.x + v.y * v.y + v.z * v.z + v.w * v.w;
    float4 w = r2[l];
    float s2 = w.x * w.x + w.y * w.y + w.z * w.z + w.w * w.w;
#pragma unroll
    for (int off = 16; off >= 1; off >>= 1) {
        s1 += __shfl_down_sync(0xFFFFFFFFu, s1, off);
        s2 += __shfl_down_sync(0xFFFFFFFFu, s2, off);
    }
    if (l == 0) { g_n1[row] = s1; g_n2[row] = s2; }
}

// ---------------- K3: pipelined mma.sync GEMM + dual argmin ----------------
// smem rows: 264 halves (528B); A tile + double-buffered B + col-min scratch.
#define ROWB 528
#define SM_DOTS (3 * 128 * ROWB + 8192)   // 210944

__global__ void __launch_bounds__(256, 1) k_dots() {
    extern __shared__ char smem[];
    uint32_t sb = smem_u32(smem);
    const uint32_t SA = sb;
    const uint32_t SB0 = sb + 128 * ROWB;
    unsigned long long* scol = (unsigned long long*)(smem + 3 * 128 * ROWB);
    int tid = threadIdx.x, wid = tid >> 5, l = tid & 31;
    int b = blockIdx.y;
    int i0 = blockIdx.x * 128;
    const char* Ag = (const char*)(g_hl1 + ((size_t)(b * MM + i0)) * 256);
    const char* Bg = (const char*)(g_hl2 + ((size_t)b * MM) * 256);

    // prologue: A + B0 loads (group 0)
#pragma unroll
    for (int q = 0; q < 16; q++) {
        int ch = tid + q * 256;
        int row = ch >> 5, c16 = ch & 31;
        cpa16(SA + row * ROWB + c16 * 16, Ag + row * 512 + c16 * 16);
    }
#pragma unroll
    for (int q = 0; q < 16; q++) {
        int ch = tid + q * 256;
        int row = ch >> 5, c16 = ch & 31;
        cpa16(SB0 + row * ROWB + c16 * 16, Bg + row * 512 + c16 * 16);
    }
    CP_COMMIT();

    for (int v = tid; v < 1024; v += 256) scol[v] = ~0ULL;

    int m0w = (wid >> 2) * 64;
    int n0w = (wid & 3) * 32;

    int rowA = (l & 7) + ((l >> 3) & 1) * 8;
    int koffA = (l >> 4) * 8;
    uint32_t aBase = SA + (uint32_t)(m0w + rowA) * ROWB + koffA * 2;
    int rowB = (l & 7) + ((l >> 4) & 1) * 8;
    int koffB = ((l >> 3) & 1) * 8;
    uint32_t bLane = (uint32_t)(n0w + rowB) * ROWB + koffB * 2;

    float n1r[4][2];
#pragma unroll
    for (int mf = 0; mf < 4; mf++)
#pragma unroll
        for (int h = 0; h < 2; h++)
            n1r[mf][h] = g_n1[b * MM + i0 + m0w + mf * 16 + (l >> 2) + h * 8];

    unsigned long long run1[4][2];
#pragma unroll
    for (int mf = 0; mf < 4; mf++) { run1[mf][0] = ~0ULL; run1[mf][1] = ~0ULL; }

#pragma unroll 1
    for (int jt = 0; jt < 8; jt++) {
        int j0 = jt * 128;
        __syncthreads();  // all warps done reading the buffer we are about to overwrite
        if (jt < 7) {
            const char* src = Bg + (size_t)(jt + 1) * 128 * 512;
            uint32_t dstb = SB0 + (uint32_t)((jt + 1) & 1) * 128 * ROWB;
#pragma unroll
            for (int q = 0; q < 16; q++) {
                int ch = tid + q * 256;
                int row = ch >> 5, c16 = ch & 31;
                cpa16(dstb + row * ROWB + c16 * 16, src + row * 512 + c16 * 16);
            }
            CP_COMMIT();
            CP_WAIT(1);
        } else {
            CP_WAIT(0);
        }
        __syncthreads();  // B_jt visible to all threads

        uint32_t bBase = SB0 + (uint32_t)(jt & 1) * 128 * ROWB + bLane;

        float acc[4][4][4];
#pragma unroll
        for (int mf = 0; mf < 4; mf++)
#pragma unroll
            for (int nf = 0; nf < 4; nf++)
#pragma unroll
                for (int r = 0; r < 4; r++) acc[mf][nf][r] = 0.f;

        // 3 segments x 8 k16-steps: (Ahi,Bhi), (Ahi,Blo), (Alo,Bhi)
#pragma unroll 2
        for (int ks = 0; ks < 24; ks++) {
            uint32_t aoff = (((ks >> 3) == 2) ? 256u : 0u) + (uint32_t)(ks & 7) * 32u;
            uint32_t boff = (((ks >> 3) == 1) ? 256u : 0u) + (uint32_t)(ks & 7) * 32u;
            uint32_t a[4][4];
#pragma unroll
            for (int mf = 0; mf < 4; mf++)
                LDMX4(a[mf][0], a[mf][1], a[mf][2], a[mf][3],
                      aBase + (uint32_t)mf * 16 * ROWB + aoff);
#pragma unroll
            for (int np = 0; np < 2; np++) {
                uint32_t bf0, bf1, bf2, bf3;
                LDMX4(bf0, bf1, bf2, bf3,
                      bBase + (uint32_t)np * 16 * ROWB + boff);
#pragma unroll
                for (int mf = 0; mf < 4; mf++) {
                    MMA16816(acc[mf][np * 2],     a[mf][0], a[mf][1], a[mf][2], a[mf][3], bf0, bf1);
                    MMA16816(acc[mf][np * 2 + 1], a[mf][0], a[mf][1], a[mf][2], a[mf][3], bf2, bf3);
                }
            }
        }

        // ---- epilogue: dual argmin over this 128x128 tile ----
        float n2r[4][2];
#pragma unroll
        for (int nf = 0; nf < 4; nf++)
#pragma unroll
            for (int p = 0; p < 2; p++)
                n2r[nf][p] = g_n2[b * MM + j0 + n0w + nf * 8 + (l & 3) * 2 + p];

        // row minima (idx1)
#pragma unroll
        for (int mf = 0; mf < 4; mf++)
#pragma unroll
            for (int h = 0; h < 2; h++) {
                unsigned long long pk = ~0ULL;
#pragma unroll
                for (int nf = 0; nf < 4; nf++)
#pragma unroll
                    for (int p = 0; p < 2; p++) {
                        float val = fmaf(-2.f, acc[mf][nf][h * 2 + p], n2r[nf][p]);
                        int j = j0 + n0w + nf * 8 + (l & 3) * 2 + p;
                        unsigned long long e =
                            ((unsigned long long)fenc(val) << 32) | (unsigned)j;
                        if (e < pk) pk = e;
                    }
                unsigned long long o;
                o = __shfl_xor_sync(0xFFFFFFFFu, pk, 1); if (o < pk) pk = o;
                o = __shfl_xor_sync(0xFFFFFFFFu, pk, 2); if (o < pk) pk = o;
                if (pk < run1[mf][h]) run1[mf][h] = pk;
            }

        // col minima (idx2) -> shared accumulation
#pragma unroll
        for (int nf = 0; nf < 4; nf++)
#pragma unroll
            for (int p = 0; p < 2; p++) {
                unsigned long long pk = ~0ULL;
#pragma unroll
                for (int mf = 0; mf < 4; mf++)
#pragma unroll
                    for (int h = 0; h < 2; h++) {
                        float val = fmaf(-2.f, acc[mf][nf][h * 2 + p], n1r[mf][h]);
                        int i = i0 + m0w + mf * 16 + (l >> 2) + h * 8;
                        unsigned long long e =
                            ((unsigned long long)fenc(val) << 32) | (unsigned)i;
                        if (e < pk) pk = e;
                    }
                unsigned long long o;
                o = __shfl_xor_sync(0xFFFFFFFFu, pk, 4);  if (o < pk) pk = o;
                o = __shfl_xor_sync(0xFFFFFFFFu, pk, 8);  if (o < pk) pk = o;
                o = __shfl_xor_sync(0xFFFFFFFFu, pk, 16); if (o < pk) pk = o;
                if (l < 4)
                    atomicMin(&scol[j0 + n0w + nf * 8 + (l & 3) * 2 + p], pk);
            }
    }

    // flush row minima
#pragma unroll
    for (int mf = 0; mf < 4; mf++)
#pragma unroll
        for (int h = 0; h < 2; h++)
            if ((l & 3) == 0)
                atomicMin(&g_idx1p[b * MM + i0 + m0w + mf * 16 + (l >> 2) + h * 8],
                          run1[mf][h]);

    // flush col minima
    __syncthreads();
    for (int v = tid; v < 1024; v += 256)
        atomicMin(&g_idx2p[b * MM + v], scol[v]);
}

// ---------------- K4: gather NN + vicreg statistics (coalesced) ----------------
__global__ void __launch_bounds__(128) k_stats() {
    __shared__ __align__(16) float Xs[2][16][132];
    __shared__ float sred[12];
    int i = blockIdx.x;
    int p = blockIdx.y;
    int c = threadIdx.x;
    const float* tx_ = p ? g_t2 : g_t1;
    const float* ty_ = p ? g_t1 : g_t2;

    float x[16], y[16];
#pragma unroll
    for (int b = 0; b < 16; b++) {
        int j = (int)((p ? g_idx2p[b * MM + i] : g_idx1p[b * MM + i]) & 0xFFFFFFFFULL);
        x[b] = tx_[((size_t)b * MM + i) * CC + c];
        y[b] = ty_[((size_t)b * MM + j) * CC + c];
    }

    float repr = 0.f;
#pragma unroll
    for (int b = 0; b < 16; b++) { float d = x[b] - y[b]; repr += d * d; }

    float mux = 0.f, muy = 0.f;
#pragma unroll
    for (int b = 0; b < 16; b++) { mux += x[b]; muy += y[b]; }
    mux *= (1.f / 16.f); muy *= (1.f / 16.f);

    float sx = 0.f, sy = 0.f;
#pragma unroll
    for (int b = 0; b < 16; b++) {
        x[b] -= mux; sx += x[b] * x[b];
        y[b] -= muy; sy += y[b] * y[b];
    }
    float stdp = fmaxf(0.f, 1.f - sqrtf(sx * (1.f / 15.f) + 1e-4f))
               + fmaxf(0.f, 1.f - sqrtf(sy * (1.f / 15.f) + 1e-4f));
    float S2 = sx * sx + sy * sy;

#pragma unroll
    for (int b = 0; b < 16; b++) {
        Xs[0][b][c] = x[b];
        Xs[1][b][c] = y[b];
    }
    __syncthreads();

    float covpart = -S2;
    for (int d = c; d < 272; d += 128) {
        int tpr = (d >= 136) ? 1 : 0;
        int pr = d - tpr * 136;
        int a = 0, rem = pr;
        while (rem >= 16 - a) { rem -= 16 - a; a++; }
        int b2 = a + rem;
        const float4* ra = (const float4*)&Xs[tpr][a][0];
        const float4* rb = (const float4*)&Xs[tpr][b2][0];
        float g = 0.f;
#pragma unroll
        for (int q = 0; q < 32; q++) {
            float4 va = ra[q], vb = rb[q];
            g += va.x * vb.x + va.y * vb.y + va.z * vb.z + va.w * vb.w;
        }
        float w = (a == b2) ? 1.f : 2.f;
        covpart += w * g * g;
    }

    float v0 = repr, v1 = stdp, v2 = covpart;
#pragma unroll
    for (int off = 16; off >= 1; off >>= 1) {
        v0 += __shfl_down_sync(0xFFFFFFFFu, v0, off);
        v1 += __shfl_down_sync(0xFFFFFFFFu, v1, off);
        v2 += __shfl_down_sync(0xFFFFFFFFu, v2, off);
    }
    int w = c >> 5;
    if ((c & 31) == 0) { sred[w] = v0; sred[4 + w] = v1; sred[8 + w] = v2; }
    __syncthreads();
    if (c == 0) {
        int blk = p * 1024 + i;
        g_part[0][blk] = sred[0] + sred[1] + sred[2] + sred[3];
        g_part[1][blk] = sred[4] + sred[5] + sred[6] + sred[7];
        g_part[2][blk] = sred[8] + sred[9] + sred[10] + sred[11];
    }
}

// ---------------- K5: final reduction + scaling ----------------
__global__ void __launch_bounds__(1024) k_final(float* __restrict__ out) {
    __shared__ float sred[32];
    int t = threadIdx.x;
    for (int s = 0; s < 3; s++) {
        float v = g_part[s][t] + g_part[s][t + 1024];
#pragma unroll
        for (int off = 16; off >= 1; off >>= 1)
            v += __shfl_down_sync(0xFFFFFFFFu, v, off);
        if ((t & 31) == 0) sred[t >> 5] = v;
        __syncthreads();
        if (t == 0) {
            float tot = 0.f;
            for (int w2 = 0; w2 < 32; w2++) tot += sred[w2];
            float scale;
            if (s == 0)      scale = 25.f / (2.f * 2097152.f);
            else if (s == 1) scale = 25.f / (4.f * 131072.f);
            else             scale = 1.f / (225.f * 524288.f);
            out[s] = tot * scale;
        }
        __syncthreads();
    }
}

// ---------------- launch ----------------
extern "C" void kernel_launch(void* const* d_in, const int* in_sizes, int n_in,
                              void* d_out, int out_size) {
    const float* e1 = (const float*)d_in[0];
    const float* e2 = (const float*)d_in[1];
    float* out = (float*)d_out;
    (void)in_sizes; (void)n_in; (void)out_size;

    cudaFuncSetAttribute(k_dots, cudaFuncAttributeMaxDynamicSharedMemorySize, SM_DOTS);

    k_prep<<<dim3(32, 4, 16), dim3(32, 8)>>>(e1, e2);
    k_norms<<<BM / 8, 256>>>();
    k_dots<<<dim3(8, 16), 256, SM_DOTS>>>();
    k_stats<<<dim3(MM, 2), 128>>>();
    k_final<<<1, 1024>>>(out);
}

// round 6
// speedup vs baseline: 3.3540x; 1.2474x over previous
#include <cuda_runtime.h>
#include <cuda_bf16.h>
#include <stdint.h>

#define BB 16
#define MM 1024
#define CC 128
#define BM (BB*MM)

// ---------------- device scratch ----------------
__device__ float g_n1[BM];
__device__ float g_n2[BM];
__device__ unsigned long long g_idx1p[BM];
__device__ unsigned long long g_idx2p[BM];
__device__ float g_part[3][2048];
__device__ float g_t1[(size_t)BM * CC];        // fp32 (b,i,c)
__device__ float g_t2[(size_t)BM * CC];
__device__ unsigned short g_hl1[(size_t)BM * 256];  // rows [hi(128)|lo(128)] bf16
__device__ unsigned short g_hl2[(size_t)BM * 256];

// ---------------- helpers ----------------
__device__ __forceinline__ uint32_t smem_u32(const void* p) {
    uint32_t a;
    asm("{ .reg .u64 t; cvta.to.shared.u64 t, %1; cvt.u32.u64 %0, t; }" : "=r"(a) : "l"(p));
    return a;
}
__device__ __forceinline__ unsigned int fenc(float f) {
    unsigned int u = __float_as_uint(f);
    return (u & 0x80000000u) ? ~u : (u | 0x80000000u);
}
__device__ __forceinline__ void cpa16(uint32_t dst, const void* src) {
    asm volatile("cp.async.cg.shared.global [%0], [%1], 16;" :: "r"(dst), "l"(src));
}
#define CP_COMMIT() asm volatile("cp.async.commit_group;" ::: "memory")
#define CP_WAIT(n)  asm volatile("cp.async.wait_group %0;" :: "n"(n) : "memory")

#define LDMX4(r0, r1, r2, r3, addr) \
    asm volatile("ldmatrix.sync.aligned.m8n8.x4.shared.b16 {%0,%1,%2,%3}, [%4];" \
        : "=r"(r0), "=r"(r1), "=r"(r2), "=r"(r3) : "r"(addr))

#define MMA16816(d, a0, a1, a2, a3, b0, b1) \
    asm volatile("mma.sync.aligned.m16n8k16.row.col.f32.bf16.bf16.f32 " \
        "{%0,%1,%2,%3}, {%4,%5,%6,%7}, {%8,%9}, {%0,%1,%2,%3};" \
        : "+f"((d)[0]), "+f"((d)[1]), "+f"((d)[2]), "+f"((d)[3]) \
        : "r"(a0), "r"(a1), "r"(a2), "r"(a3), "r"(b0), "r"(b1))

// ---------------- K1: fused transpose + bf16 hi/lo + norms + idx init ----------------
__global__ void __launch_bounds__(256) k_prep(const float* __restrict__ e1,
                                              const float* __restrict__ e2) {
    __shared__ float sm[2][32][33];
    int b = blockIdx.y;
    int i0 = blockIdx.x * 32;
    int tx = threadIdx.x, ty = threadIdx.y;
    const float* s1 = e1 + (size_t)b * CC * MM;
    const float* s2 = e2 + (size_t)b * CC * MM;

    if (ty == 0) {
        g_idx1p[b * MM + i0 + tx] = ~0ULL;
        g_idx2p[b * MM + i0 + tx] = ~0ULL;
    }

    float ns1[4] = {0.f, 0.f, 0.f, 0.f};
    float ns2[4] = {0.f, 0.f, 0.f, 0.f};

#pragma unroll 1
    for (int cc = 0; cc < 4; cc++) {
        __syncthreads();
#pragma unroll
        for (int q = 0; q < 4; q++) {
            int c = cc * 32 + ty + q * 8;
            sm[0][ty + q * 8][tx] = s1[(size_t)c * MM + i0 + tx];
            sm[1][ty + q * 8][tx] = s2[(size_t)c * MM + i0 + tx];
        }
        __syncthreads();
#pragma unroll
        for (int q = 0; q < 4; q++) {
            int i = i0 + ty + q * 8;
            size_t row = (size_t)b * MM + i;
            int c = cc * 32 + tx;
            float v1 = sm[0][tx][ty + q * 8];
            float v2 = sm[1][tx][ty + q * 8];
            g_t1[row * CC + c] = v1;
            g_t2[row * CC + c] = v2;
            __nv_bfloat16 h1 = __float2bfloat16(v1);
            __nv_bfloat16 h2 = __float2bfloat16(v2);
            g_hl1[row * 256 + c]       = __bfloat16_as_ushort(h1);
            g_hl1[row * 256 + 128 + c] = __bfloat16_as_ushort(__float2bfloat16(v1 - __bfloat162float(h1)));
            g_hl2[row * 256 + c]       = __bfloat16_as_ushort(h2);
            g_hl2[row * 256 + 128 + c] = __bfloat16_as_ushort(__float2bfloat16(v2 - __bfloat162float(h2)));
            ns1[q] = fmaf(v1, v1, ns1[q]);
            ns2[q] = fmaf(v2, v2, ns2[q]);
        }
    }

#pragma unroll
    for (int q = 0; q < 4; q++) {
        float s1v = ns1[q], s2v = ns2[q];
#pragma unroll
        for (int off = 16; off >= 1; off >>= 1) {
            s1v += __shfl_down_sync(0xFFFFFFFFu, s1v, off);
            s2v += __shfl_down_sync(0xFFFFFFFFu, s2v, off);
        }
        if (tx == 0) {
            g_n1[b * MM + i0 + ty + q * 8] = s1v;
            g_n2[b * MM + i0 + ty + q * 8] = s2v;
        }
    }
}

// ---------------- K2: pipelined mma.sync GEMM + dual argmin (16 warps) ----------------
#define ROWB 528
#define SM_DOTS (3 * 128 * ROWB + 8192)   // 210944

__global__ void __launch_bounds__(512, 1) k_dots() {
    extern __shared__ char smem[];
    uint32_t sb = smem_u32(smem);
    const uint32_t SA = sb;
    const uint32_t SB0 = sb + 128 * ROWB;
    unsigned long long* scol = (unsigned long long*)(smem + 3 * 128 * ROWB);
    int tid = threadIdx.x, wid = tid >> 5, l = tid & 31;
    int b = blockIdx.y;
    int i0 = blockIdx.x * 128;
    const char* Ag = (const char*)(g_hl1 + ((size_t)(b * MM + i0)) * 256);
    const char* Bg = (const char*)(g_hl2 + ((size_t)b * MM) * 256);

    // prologue: A + B0 loads (group 0)
#pragma unroll
    for (int q = 0; q < 8; q++) {
        int ch = tid + q * 512;
        int row = ch >> 5, c16 = ch & 31;
        cpa16(SA + row * ROWB + c16 * 16, Ag + row * 512 + c16 * 16);
    }
#pragma unroll
    for (int q = 0; q < 8; q++) {
        int ch = tid + q * 512;
        int row = ch >> 5, c16 = ch & 31;
        cpa16(SB0 + row * ROWB + c16 * 16, Bg + row * 512 + c16 * 16);
    }
    CP_COMMIT();

    for (int v = tid; v < 1024; v += 512) scol[v] = ~0ULL;

    int wy = wid >> 2, wx = wid & 3;
    int m0w = wy * 32, n0w = wx * 32;

    int rowA = (l & 7) + ((l >> 3) & 1) * 8;
    int koffA = (l >> 4) * 8;
    uint32_t aBase = SA + (uint32_t)(m0w + rowA) * ROWB + koffA * 2;
    int rowB = (l & 7) + ((l >> 4) & 1) * 8;
    int koffB = ((l >> 3) & 1) * 8;
    uint32_t bLane = (uint32_t)(n0w + rowB) * ROWB + koffB * 2;

    float n1r[2][2];
#pragma unroll
    for (int mf = 0; mf < 2; mf++)
#pragma unroll
        for (int h = 0; h < 2; h++)
            n1r[mf][h] = g_n1[b * MM + i0 + m0w + mf * 16 + (l >> 2) + h * 8];

    unsigned long long run1[2][2];
    run1[0][0] = ~0ULL; run1[0][1] = ~0ULL; run1[1][0] = ~0ULL; run1[1][1] = ~0ULL;

#pragma unroll 1
    for (int jt = 0; jt < 8; jt++) {
        int j0 = jt * 128;
        __syncthreads();  // everyone done reading buffer about to be overwritten
        if (jt < 7) {
            const char* src = Bg + (size_t)(jt + 1) * 128 * 512;
            uint32_t dstb = SB0 + (uint32_t)((jt + 1) & 1) * 128 * ROWB;
#pragma unroll
            for (int q = 0; q < 8; q++) {
                int ch = tid + q * 512;
                int row = ch >> 5, c16 = ch & 31;
                cpa16(dstb + row * ROWB + c16 * 16, src + row * 512 + c16 * 16);
            }
            CP_COMMIT();
            CP_WAIT(1);
        } else {
            CP_WAIT(0);
        }
        __syncthreads();  // current B tile visible

        uint32_t bBase = SB0 + (uint32_t)(jt & 1) * 128 * ROWB + bLane;

        float acc[2][4][4];
#pragma unroll
        for (int mf = 0; mf < 2; mf++)
#pragma unroll
            for (int nf = 0; nf < 4; nf++)
#pragma unroll
                for (int r = 0; r < 4; r++) acc[mf][nf][r] = 0.f;

        // each k16: load Ahi/Alo/Bhi/Blo once, accumulate hh + hl + lh
#pragma unroll 2
        for (int ks = 0; ks < 8; ks++) {
            uint32_t ao = (uint32_t)ks * 32u;
            uint32_t ahi[2][4], alo[2][4], bhi[2][4], blo[2][4];
#pragma unroll
            for (int mf = 0; mf < 2; mf++) {
                LDMX4(ahi[mf][0], ahi[mf][1], ahi[mf][2], ahi[mf][3],
                      aBase + (uint32_t)mf * 16 * ROWB + ao);
                LDMX4(alo[mf][0], alo[mf][1], alo[mf][2], alo[mf][3],
                      aBase + (uint32_t)mf * 16 * ROWB + ao + 256);
            }
#pragma unroll
            for (int np = 0; np < 2; np++) {
                LDMX4(bhi[np][0], bhi[np][1], bhi[np][2], bhi[np][3],
                      bBase + (uint32_t)np * 16 * ROWB + ao);
                LDMX4(blo[np][0], blo[np][1], blo[np][2], blo[np][3],
                      bBase + (uint32_t)np * 16 * ROWB + ao + 256);
            }
#pragma unroll
            for (int mf = 0; mf < 2; mf++)
#pragma unroll
                for (int np = 0; np < 2; np++) {
                    MMA16816(acc[mf][np * 2],     ahi[mf][0], ahi[mf][1], ahi[mf][2], ahi[mf][3], bhi[np][0], bhi[np][1]);
                    MMA16816(acc[mf][np * 2 + 1], ahi[mf][0], ahi[mf][1], ahi[mf][2], ahi[mf][3], bhi[np][2], bhi[np][3]);
                    MMA16816(acc[mf][np * 2],     ahi[mf][0], ahi[mf][1], ahi[mf][2], ahi[mf][3], blo[np][0], blo[np][1]);
                    MMA16816(acc[mf][np * 2 + 1], ahi[mf][0], ahi[mf][1], ahi[mf][2], ahi[mf][3], blo[np][2], blo[np][3]);
                    MMA16816(acc[mf][np * 2],     alo[mf][0], alo[mf][1], alo[mf][2], alo[mf][3], bhi[np][0], bhi[np][1]);
                    MMA16816(acc[mf][np * 2 + 1], alo[mf][0], alo[mf][1], alo[mf][2], alo[mf][3], bhi[np][2], bhi[np][3]);
                }
        }

        // ---- epilogue: dual argmin over this 128x128 tile ----
        float n2r[4][2];
#pragma unroll
        for (int nf = 0; nf < 4; nf++)
#pragma unroll
            for (int p = 0; p < 2; p++)
                n2r[nf][p] = g_n2[b * MM + j0 + n0w + nf * 8 + (l & 3) * 2 + p];

        // row minima (idx1)
#pragma unroll
        for (int mf = 0; mf < 2; mf++)
#pragma unroll
            for (int h = 0; h < 2; h++) {
                unsigned long long pk = ~0ULL;
#pragma unroll
                for (int nf = 0; nf < 4; nf++)
#pragma unroll
                    for (int p = 0; p < 2; p++) {
                        float val = fmaf(-2.f, acc[mf][nf][h * 2 + p], n2r[nf][p]);
                        int j = j0 + n0w + nf * 8 + (l & 3) * 2 + p;
                        unsigned long long e =
                            ((unsigned long long)fenc(val) << 32) | (unsigned)j;
                        if (e < pk) pk = e;
                    }
                unsigned long long o;
                o = __shfl_xor_sync(0xFFFFFFFFu, pk, 1); if (o < pk) pk = o;
                o = __shfl_xor_sync(0xFFFFFFFFu, pk, 2); if (o < pk) pk = o;
                if (pk < run1[mf][h]) run1[mf][h] = pk;
            }

        // col minima (idx2) -> shared accumulation
#pragma unroll
        for (int nf = 0; nf < 4; nf++)
#pragma unroll
            for (int p = 0; p < 2; p++) {
                unsigned long long pk = ~0ULL;
#pragma unroll
                for (int mf = 0; mf < 2; mf++)
#pragma unroll
                    for (int h = 0; h < 2; h++) {
                        float val = fmaf(-2.f, acc[mf][nf][h * 2 + p], n1r[mf][h]);
                        int i = i0 + m0w + mf * 16 + (l >> 2) + h * 8;
                        unsigned long long e =
                            ((unsigned long long)fenc(val) << 32) | (unsigned)i;
                        if (e < pk) pk = e;
                    }
                unsigned long long o;
                o = __shfl_xor_sync(0xFFFFFFFFu, pk, 4);  if (o < pk) pk = o;
                o = __shfl_xor_sync(0xFFFFFFFFu, pk, 8);  if (o < pk) pk = o;
                o = __shfl_xor_sync(0xFFFFFFFFu, pk, 16); if (o < pk) pk = o;
                if (l < 4)
                    atomicMin(&scol[j0 + n0w + nf * 8 + (l & 3) * 2 + p], pk);
            }
    }

    // flush row minima
#pragma unroll
    for (int mf = 0; mf < 2; mf++)
#pragma unroll
        for (int h = 0; h < 2; h++)
            if ((l & 3) == 0)
                atomicMin(&g_idx1p[b * MM + i0 + m0w + mf * 16 + (l >> 2) + h * 8],
                          run1[mf][h]);

    // flush col minima
    __syncthreads();
    for (int v = tid; v < 1024; v += 512)
        atomicMin(&g_idx2p[b * MM + v], scol[v]);
}

// ---------------- K3: gather NN + vicreg stats; Gram via one-warp mma ----------------
// covpart = ||XX^T||_F^2 (FULL 16x16 Gram, batch diag INCLUDED)  -  sum_c sx^2
// (the subtracted diagonal is the 128x128 CHANNEL diagonal = per-channel sx^2)
__global__ void __launch_bounds__(128) k_stats() {
    __shared__ __align__(16) __nv_bfloat16 Xb[2][16][136];  // row stride 272B
    __shared__ float sred[12];
    int i = blockIdx.x;
    int p = blockIdx.y;
    int c = threadIdx.x;
    const float* tx_ = p ? g_t2 : g_t1;
    const float* ty_ = p ? g_t1 : g_t2;

    float x[16], y[16];
#pragma unroll
    for (int b = 0; b < 16; b++) {
        int j = (int)((p ? g_idx2p[b * MM + i] : g_idx1p[b * MM + i]) & 0xFFFFFFFFULL);
        x[b] = tx_[((size_t)b * MM + i) * CC + c];
        y[b] = ty_[((size_t)b * MM + j) * CC + c];
    }

    float repr = 0.f;
#pragma unroll
    for (int b = 0; b < 16; b++) { float d = x[b] - y[b]; repr += d * d; }

    float mux = 0.f, muy = 0.f;
#pragma unroll
    for (int b = 0; b < 16; b++) { mux += x[b]; muy += y[b]; }
    mux *= (1.f / 16.f); muy *= (1.f / 16.f);

    float sx = 0.f, sy = 0.f;
#pragma unroll
    for (int b = 0; b < 16; b++) {
        x[b] -= mux; sx += x[b] * x[b];
        y[b] -= muy; sy += y[b] * y[b];
    }
    float stdp = fmaxf(0.f, 1.f - sqrtf(sx * (1.f / 15.f) + 1e-4f))
               + fmaxf(0.f, 1.f - sqrtf(sy * (1.f / 15.f) + 1e-4f));
    float S2 = sx * sx + sy * sy;   // channel-diagonal contribution (exact fp32)

    // store centered rows as bf16 for the Gram mma
#pragma unroll
    for (int b = 0; b < 16; b++) {
        Xb[0][b][c] = __float2bfloat16(x[b]);
        Xb[1][b][c] = __float2bfloat16(y[b]);
    }
    __syncthreads();

    float covpart = -S2;
    int wid = c >> 5, l = c & 31;
    if (wid == 0) {
        int rowA = (l & 7) + ((l >> 3) & 1) * 8;
        int koffA = (l >> 4) * 8;
        int rowB = (l & 7) + ((l >> 4) & 1) * 8;
        int koffB = ((l >> 3) & 1) * 8;
        uint32_t base0 = smem_u32(&Xb[0][0][0]);
#pragma unroll
        for (int t = 0; t < 2; t++) {
            uint32_t tb = base0 + (uint32_t)t * 16 * 272;
            uint32_t aB = tb + (uint32_t)rowA * 272 + koffA * 2;
            uint32_t bB = tb + (uint32_t)rowB * 272 + koffB * 2;
            float acc[8];
#pragma unroll
            for (int r = 0; r < 8; r++) acc[r] = 0.f;
#pragma unroll
            for (int ks = 0; ks < 8; ks++) {
                uint32_t a0, a1, a2, a3, b0, b1, b2, b3;
                LDMX4(a0, a1, a2, a3, aB + ks * 32);
                LDMX4(b0, b1, b2, b3, bB + ks * 32);
                MMA16816(acc,     a0, a1, a2, a3, b0, b1);
                MMA16816(acc + 4, a0, a1, a2, a3, b2, b3);
            }
            // FULL Frobenius norm of the 16x16 batch Gram (no masking)
#pragma unroll
            for (int r = 0; r < 8; r++)
                covpart = fmaf(acc[r], acc[r], covpart);
        }
    }

    float v0 = repr, v1 = stdp, v2 = covpart;
#pragma unroll
    for (int off = 16; off >= 1; off >>= 1) {
        v0 += __shfl_down_sync(0xFFFFFFFFu, v0, off);
        v1 += __shfl_down_sync(0xFFFFFFFFu, v1, off);
        v2 += __shfl_down_sync(0xFFFFFFFFu, v2, off);
    }
    if ((c & 31) == 0) { sred[wid] = v0; sred[4 + wid] = v1; sred[8 + wid] = v2; }
    __syncthreads();
    if (c == 0) {
        int blk = p * 1024 + i;
        g_part[0][blk] = sred[0] + sred[1] + sred[2] + sred[3];
        g_part[1][blk] = sred[4] + sred[5] + sred[6] + sred[7];
        g_part[2][blk] = sred[8] + sred[9] + sred[10] + sred[11];
    }
}

// ---------------- K4: final reduction + scaling ----------------
__global__ void __launch_bounds__(1024) k_final(float* __restrict__ out) {
    __shared__ float sred[32];
    int t = threadIdx.x;
    for (int s = 0; s < 3; s++) {
        float v = g_part[s][t] + g_part[s][t + 1024];
#pragma unroll
        for (int off = 16; off >= 1; off >>= 1)
            v += __shfl_down_sync(0xFFFFFFFFu, v, off);
        if ((t & 31) == 0) sred[t >> 5] = v;
        __syncthreads();
        if (t == 0) {
            float tot = 0.f;
            for (int w2 = 0; w2 < 32; w2++) tot += sred[w2];
            float scale;
            if (s == 0)      scale = 25.f / (2.f * 2097152.f);
            else if (s == 1) scale = 25.f / (4.f * 131072.f);
            else             scale = 1.f / (225.f * 524288.f);
            out[s] = tot * scale;
        }
        __syncthreads();
    }
}

// ---------------- launch ----------------
extern "C" void kernel_launch(void* const* d_in, const int* in_sizes, int n_in,
                              void* d_out, int out_size) {
    const float* e1 = (const float*)d_in[0];
    const float* e2 = (const float*)d_in[1];
    float* out = (float*)d_out;
    (void)in_sizes; (void)n_in; (void)out_size;

    cudaFuncSetAttribute(k_dots, cudaFuncAttributeMaxDynamicSharedMemorySize, SM_DOTS);

    k_prep<<<dim3(32, 16), dim3(32, 8)>>>(e1, e2);
    k_dots<<<dim3(8, 16), 512, SM_DOTS>>>();
    k_stats<<<dim3(MM, 2), 128>>>();
    k_final<<<1, 1024>>>(out);
}

// round 7
// speedup vs baseline: 3.7700x; 1.1240x over previous
#include <cuda_runtime.h>
#include <cuda_bf16.h>
#include <stdint.h>

#define BB 16
#define MM 1024
#define CC 128
#define BM (BB*MM)

// ---------------- device scratch ----------------
__device__ float g_n1[BM];
__device__ float g_n2[BM];
__device__ unsigned long long g_idx1p[BM];
__device__ unsigned long long g_idx2p[BM];
__device__ float g_part[3][2048];
__device__ __nv_bfloat16 g_hl1[(size_t)BM * 256];  // rows [hi(128)|lo(128)]
__device__ __nv_bfloat16 g_hl2[(size_t)BM * 256];

// ---------------- helpers ----------------
__device__ __forceinline__ uint32_t smem_u32(const void* p) {
    uint32_t a;
    asm("{ .reg .u64 t; cvta.to.shared.u64 t, %1; cvt.u32.u64 %0, t; }" : "=r"(a) : "l"(p));
    return a;
}
__device__ __forceinline__ unsigned int fenc(float f) {
    unsigned int u = __float_as_uint(f);
    return (u & 0x80000000u) ? ~u : (u | 0x80000000u);
}
__device__ __forceinline__ void cpa16(uint32_t dst, const void* src) {
    asm volatile("cp.async.cg.shared.global [%0], [%1], 16;" :: "r"(dst), "l"(src));
}
#define CP_COMMIT() asm volatile("cp.async.commit_group;" ::: "memory")
#define CP_WAIT(n)  asm volatile("cp.async.wait_group %0;" :: "n"(n) : "memory")

#define LDMX4(r0, r1, r2, r3, addr) \
    asm volatile("ldmatrix.sync.aligned.m8n8.x4.shared.b16 {%0,%1,%2,%3}, [%4];" \
        : "=r"(r0), "=r"(r1), "=r"(r2), "=r"(r3) : "r"(addr))

#define MMA16816(d, a0, a1, a2, a3, b0, b1) \
    asm volatile("mma.sync.aligned.m16n8k16.row.col.f32.bf16.bf16.f32 " \
        "{%0,%1,%2,%3}, {%4,%5,%6,%7}, {%8,%9}, {%0,%1,%2,%3};" \
        : "+f"((d)[0]), "+f"((d)[1]), "+f"((d)[2]), "+f"((d)[3]) \
        : "r"(a0), "r"(a1), "r"(a2), "r"(a3), "r"(b0), "r"(b1))

// ---------------- K1: fused transpose + bf16 hi/lo + norms + idx init ----------------
__global__ void __launch_bounds__(256) k_prep(const float* __restrict__ e1,
                                              const float* __restrict__ e2) {
    __shared__ float sm[2][32][33];
    int b = blockIdx.y;
    int i0 = blockIdx.x * 32;
    int tx = threadIdx.x, ty = threadIdx.y;
    const float* s1 = e1 + (size_t)b * CC * MM;
    const float* s2 = e2 + (size_t)b * CC * MM;

    if (ty == 0) {
        g_idx1p[b * MM + i0 + tx] = ~0ULL;
        g_idx2p[b * MM + i0 + tx] = ~0ULL;
    }

    float ns1[4] = {0.f, 0.f, 0.f, 0.f};
    float ns2[4] = {0.f, 0.f, 0.f, 0.f};

#pragma unroll 1
    for (int cc = 0; cc < 4; cc++) {
        __syncthreads();
#pragma unroll
        for (int q = 0; q < 4; q++) {
            int c = cc * 32 + ty + q * 8;
            sm[0][ty + q * 8][tx] = s1[(size_t)c * MM + i0 + tx];
            sm[1][ty + q * 8][tx] = s2[(size_t)c * MM + i0 + tx];
        }
        __syncthreads();
#pragma unroll
        for (int q = 0; q < 4; q++) {
            int i = i0 + ty + q * 8;
            size_t row = (size_t)b * MM + i;
            int c = cc * 32 + tx;
            float v1 = sm[0][tx][ty + q * 8];
            float v2 = sm[1][tx][ty + q * 8];
            __nv_bfloat16 h1 = __float2bfloat16(v1);
            __nv_bfloat16 h2 = __float2bfloat16(v2);
            g_hl1[row * 256 + c]       = h1;
            g_hl1[row * 256 + 128 + c] = __float2bfloat16(v1 - __bfloat162float(h1));
            g_hl2[row * 256 + c]       = h2;
            g_hl2[row * 256 + 128 + c] = __float2bfloat16(v2 - __bfloat162float(h2));
            ns1[q] = fmaf(v1, v1, ns1[q]);
            ns2[q] = fmaf(v2, v2, ns2[q]);
        }
    }

#pragma unroll
    for (int q = 0; q < 4; q++) {
        float s1v = ns1[q], s2v = ns2[q];
#pragma unroll
        for (int off = 16; off >= 1; off >>= 1) {
            s1v += __shfl_down_sync(0xFFFFFFFFu, s1v, off);
            s2v += __shfl_down_sync(0xFFFFFFFFu, s2v, off);
        }
        if (tx == 0) {
            g_n1[b * MM + i0 + ty + q * 8] = s1v;
            g_n2[b * MM + i0 + ty + q * 8] = s2v;
        }
    }
}

// ---------------- K2: 2-segment mma GEMM + dual argmin (16 warps) ----------------
// dot ~= Ahi*Bhi + Ahi*Blo  (drops Alo*Bhi and Alo*Blo; d2 error ~0.04)
#define ROWA 272
#define ROWB 528
#define SM_A_SZ (128 * ROWA)                    // 34816
#define SM_SCOL (SM_A_SZ + 2 * 128 * ROWB)      // 169984
#define SM_DOTS (SM_SCOL + 8192)                // 178176

__global__ void __launch_bounds__(512, 1) k_dots() {
    extern __shared__ char smem[];
    uint32_t sb = smem_u32(smem);
    const uint32_t SA = sb;
    const uint32_t SB0 = sb + SM_A_SZ;
    unsigned long long* scol = (unsigned long long*)(smem + SM_SCOL);
    int tid = threadIdx.x, wid = tid >> 5, l = tid & 31;
    int b = blockIdx.y;
    int i0 = blockIdx.x * 128;
    const char* Ag = (const char*)(g_hl1 + ((size_t)(b * MM + i0)) * 256);
    const char* Bg = (const char*)(g_hl2 + ((size_t)b * MM) * 256);

    // prologue: A-hi (256B/row) + full B0 (512B/row), one cp.async group
#pragma unroll
    for (int q = 0; q < 4; q++) {
        int ch = tid + q * 512;           // 2048 chunks: 128 rows x 16
        int row = ch >> 4, c16 = ch & 15;
        cpa16(SA + row * ROWA + c16 * 16, Ag + row * 512 + c16 * 16);
    }
#pragma unroll
    for (int q = 0; q < 8; q++) {
        int ch = tid + q * 512;           // 4096 chunks: 128 rows x 32
        int row = ch >> 5, c16 = ch & 31;
        cpa16(SB0 + row * ROWB + c16 * 16, Bg + row * 512 + c16 * 16);
    }
    CP_COMMIT();

    for (int v = tid; v < 1024; v += 512) scol[v] = ~0ULL;

    int wy = wid >> 2, wx = wid & 3;
    int m0w = wy * 32, n0w = wx * 32;

    int rowA = (l & 7) + ((l >> 3) & 1) * 8;
    int koffA = (l >> 4) * 8;
    uint32_t aBase = SA + (uint32_t)(m0w + rowA) * ROWA + koffA * 2;
    int rowB = (l & 7) + ((l >> 4) & 1) * 8;
    int koffB = ((l >> 3) & 1) * 8;
    uint32_t bLane = (uint32_t)(n0w + rowB) * ROWB + koffB * 2;

    float n1r[2][2];
#pragma unroll
    for (int mf = 0; mf < 2; mf++)
#pragma unroll
        for (int h = 0; h < 2; h++)
            n1r[mf][h] = g_n1[b * MM + i0 + m0w + mf * 16 + (l >> 2) + h * 8];

    unsigned long long run1[2][2];
    run1[0][0] = ~0ULL; run1[0][1] = ~0ULL; run1[1][0] = ~0ULL; run1[1][1] = ~0ULL;

#pragma unroll 1
    for (int jt = 0; jt < 8; jt++) {
        int j0 = jt * 128;
        __syncthreads();
        if (jt < 7) {
            const char* src = Bg + (size_t)(jt + 1) * 128 * 512;
            uint32_t dstb = SB0 + (uint32_t)((jt + 1) & 1) * 128 * ROWB;
#pragma unroll
            for (int q = 0; q < 8; q++) {
                int ch = tid + q * 512;
                int row = ch >> 5, c16 = ch & 31;
                cpa16(dstb + row * ROWB + c16 * 16, src + row * 512 + c16 * 16);
            }
            CP_COMMIT();
            CP_WAIT(1);
        } else {
            CP_WAIT(0);
        }
        __syncthreads();

        uint32_t bBase = SB0 + (uint32_t)(jt & 1) * 128 * ROWB + bLane;

        float acc[2][4][4];
#pragma unroll
        for (int mf = 0; mf < 2; mf++)
#pragma unroll
            for (int nf = 0; nf < 4; nf++)
#pragma unroll
                for (int r = 0; r < 4; r++) acc[mf][nf][r] = 0.f;

#pragma unroll 2
        for (int ks = 0; ks < 8; ks++) {
            uint32_t ao = (uint32_t)ks * 32u;
            uint32_t ahi[2][4], bhi[2][4], blo[2][4];
#pragma unroll
            for (int mf = 0; mf < 2; mf++)
                LDMX4(ahi[mf][0], ahi[mf][1], ahi[mf][2], ahi[mf][3],
                      aBase + (uint32_t)mf * 16 * ROWA + ao);
#pragma unroll
            for (int np = 0; np < 2; np++) {
                LDMX4(bhi[np][0], bhi[np][1], bhi[np][2], bhi[np][3],
                      bBase + (uint32_t)np * 16 * ROWB + ao);
                LDMX4(blo[np][0], blo[np][1], blo[np][2], blo[np][3],
                      bBase + (uint32_t)np * 16 * ROWB + ao + 256);
            }
#pragma unroll
            for (int mf = 0; mf < 2; mf++)
#pragma unroll
                for (int np = 0; np < 2; np++) {
                    MMA16816(acc[mf][np * 2],     ahi[mf][0], ahi[mf][1], ahi[mf][2], ahi[mf][3], bhi[np][0], bhi[np][1]);
                    MMA16816(acc[mf][np * 2 + 1], ahi[mf][0], ahi[mf][1], ahi[mf][2], ahi[mf][3], bhi[np][2], bhi[np][3]);
                    MMA16816(acc[mf][np * 2],     ahi[mf][0], ahi[mf][1], ahi[mf][2], ahi[mf][3], blo[np][0], blo[np][1]);
                    MMA16816(acc[mf][np * 2 + 1], ahi[mf][0], ahi[mf][1], ahi[mf][2], ahi[mf][3], blo[np][2], blo[np][3]);
                }
        }

        // ---- epilogue ----
        float n2r[4][2];
#pragma unroll
        for (int nf = 0; nf < 4; nf++)
#pragma unroll
            for (int p = 0; p < 2; p++)
                n2r[nf][p] = g_n2[b * MM + j0 + n0w + nf * 8 + (l & 3) * 2 + p];

        // row minima: per-lane running min (shfl-combine deferred to the end)
#pragma unroll
        for (int mf = 0; mf < 2; mf++)
#pragma unroll
            for (int h = 0; h < 2; h++) {
#pragma unroll
                for (int nf = 0; nf < 4; nf++)
#pragma unroll
                    for (int p = 0; p < 2; p++) {
                        float val = fmaf(-2.f, acc[mf][nf][h * 2 + p], n2r[nf][p]);
                        int j = j0 + n0w + nf * 8 + (l & 3) * 2 + p;
                        unsigned long long e =
                            ((unsigned long long)fenc(val) << 32) | (unsigned)j;
                        if (e < run1[mf][h]) run1[mf][h] = e;
                    }
            }

        // col minima -> shared accumulation (must flush per tile)
#pragma unroll
        for (int nf = 0; nf < 4; nf++)
#pragma unroll
            for (int p = 0; p < 2; p++) {
                unsigned long long pk = ~0ULL;
#pragma unroll
                for (int mf = 0; mf < 2; mf++)
#pragma unroll
                    for (int h = 0; h < 2; h++) {
                        float val = fmaf(-2.f, acc[mf][nf][h * 2 + p], n1r[mf][h]);
                        int i = i0 + m0w + mf * 16 + (l >> 2) + h * 8;
                        unsigned long long e =
                            ((unsigned long long)fenc(val) << 32) | (unsigned)i;
                        if (e < pk) pk = e;
                    }
                unsigned long long o;
                o = __shfl_xor_sync(0xFFFFFFFFu, pk, 4);  if (o < pk) pk = o;
                o = __shfl_xor_sync(0xFFFFFFFFu, pk, 8);  if (o < pk) pk = o;
                o = __shfl_xor_sync(0xFFFFFFFFu, pk, 16); if (o < pk) pk = o;
                if (l < 4)
                    atomicMin(&scol[j0 + n0w + nf * 8 + (l & 3) * 2 + p], pk);
            }
    }

    // flush row minima (combine the 4 col-groups per row, then global atomic)
#pragma unroll
    for (int mf = 0; mf < 2; mf++)
#pragma unroll
        for (int h = 0; h < 2; h++) {
            unsigned long long r = run1[mf][h], o;
            o = __shfl_xor_sync(0xFFFFFFFFu, r, 1); if (o < r) r = o;
            o = __shfl_xor_sync(0xFFFFFFFFu, r, 2); if (o < r) r = o;
            if ((l & 3) == 0)
                atomicMin(&g_idx1p[b * MM + i0 + m0w + mf * 16 + (l >> 2) + h * 8], r);
        }

    // flush col minima
    __syncthreads();
    for (int v = tid; v < 1024; v += 512)
        atomicMin(&g_idx2p[b * MM + v], scol[v]);
}

// ---------------- K3: gather NN + vicreg stats; Gram via warps 0/1 mma ----------------
__global__ void __launch_bounds__(128) k_stats() {
    __shared__ __align__(16) __nv_bfloat16 Xb[2][16][136];  // row stride 272B
    __shared__ float sred[12];
    int i = blockIdx.x;
    int p = blockIdx.y;
    int c = threadIdx.x;
    const __nv_bfloat16* tx_ = p ? g_hl2 : g_hl1;
    const __nv_bfloat16* ty_ = p ? g_hl1 : g_hl2;

    float x[16], y[16];
#pragma unroll
    for (int b = 0; b < 16; b++) {
        int j = (int)((p ? g_idx2p[b * MM + i] : g_idx1p[b * MM + i]) & 0xFFFFFFFFULL);
        size_t rx = ((size_t)b * MM + i) * 256;
        size_t ry = ((size_t)b * MM + j) * 256;
        x[b] = __bfloat162float(tx_[rx + c]) + __bfloat162float(tx_[rx + 128 + c]);
        y[b] = __bfloat162float(ty_[ry + c]) + __bfloat162float(ty_[ry + 128 + c]);
    }

    float repr = 0.f;
#pragma unroll
    for (int b = 0; b < 16; b++) { float d = x[b] - y[b]; repr += d * d; }

    float mux = 0.f, muy = 0.f;
#pragma unroll
    for (int b = 0; b < 16; b++) { mux += x[b]; muy += y[b]; }
    mux *= (1.f / 16.f); muy *= (1.f / 16.f);

    float sx = 0.f, sy = 0.f;
#pragma unroll
    for (int b = 0; b < 16; b++) {
        x[b] -= mux; sx += x[b] * x[b];
        y[b] -= muy; sy += y[b] * y[b];
    }
    float stdp = fmaxf(0.f, 1.f - sqrtf(sx * (1.f / 15.f) + 1e-4f))
               + fmaxf(0.f, 1.f - sqrtf(sy * (1.f / 15.f) + 1e-4f));
    float S2 = sx * sx + sy * sy;   // channel-diagonal contribution (exact fp32)

#pragma unroll
    for (int b = 0; b < 16; b++) {
        Xb[0][b][c] = __float2bfloat16(x[b]);
        Xb[1][b][c] = __float2bfloat16(y[b]);
    }
    __syncthreads();

    float covpart = -S2;
    int wid = c >> 5, l = c & 31;
    if (wid < 2) {
        // warp t computes Gram of tensor t (full 16x16 Frobenius)
        int t = wid;
        int rowA = (l & 7) + ((l >> 3) & 1) * 8;
        int koffA = (l >> 4) * 8;
        int rowB = (l & 7) + ((l >> 4) & 1) * 8;
        int koffB = ((l >> 3) & 1) * 8;
        uint32_t tb = smem_u32(&Xb[0][0][0]) + (uint32_t)t * 16 * 272;
        uint32_t aB = tb + (uint32_t)rowA * 272 + koffA * 2;
        uint32_t bB = tb + (uint32_t)rowB * 272 + koffB * 2;
        float acc[8];
#pragma unroll
        for (int r = 0; r < 8; r++) acc[r] = 0.f;
#pragma unroll
        for (int ks = 0; ks < 8; ks++) {
            uint32_t a0, a1, a2, a3, b0, b1, b2, b3;
            LDMX4(a0, a1, a2, a3, aB + ks * 32);
            LDMX4(b0, b1, b2, b3, bB + ks * 32);
            MMA16816(acc,     a0, a1, a2, a3, b0, b1);
            MMA16816(acc + 4, a0, a1, a2, a3, b2, b3);
        }
#pragma unroll
        for (int r = 0; r < 8; r++)
            covpart = fmaf(acc[r], acc[r], covpart);
    }

    float v0 = repr, v1 = stdp, v2 = covpart;
#pragma unroll
    for (int off = 16; off >= 1; off >>= 1) {
        v0 += __shfl_down_sync(0xFFFFFFFFu, v0, off);
        v1 += __shfl_down_sync(0xFFFFFFFFu, v1, off);
        v2 += __shfl_down_sync(0xFFFFFFFFu, v2, off);
    }
    if ((c & 31) == 0) { sred[wid] = v0; sred[4 + wid] = v1; sred[8 + wid] = v2; }
    __syncthreads();
    if (c == 0) {
        int blk = p * 1024 + i;
        g_part[0][blk] = sred[0] + sred[1] + sred[2] + sred[3];
        g_part[1][blk] = sred[4] + sred[5] + sred[6] + sred[7];
        g_part[2][blk] = sred[8] + sred[9] + sred[10] + sred[11];
    }
}

// ---------------- K4: final reduction, one block per stat ----------------
__global__ void __launch_bounds__(1024) k_final(float* __restrict__ out) {
    __shared__ float sred[32];
    int s = blockIdx.x;
    int t = threadIdx.x;
    float v = g_part[s][t] + g_part[s][t + 1024];
#pragma unroll
    for (int off = 16; off >= 1; off >>= 1)
        v += __shfl_down_sync(0xFFFFFFFFu, v, off);
    if ((t & 31) == 0) sred[t >> 5] = v;
    __syncthreads();
    if (t == 0) {
        float tot = 0.f;
        for (int w2 = 0; w2 < 32; w2++) tot += sred[w2];
        float scale;
        if (s == 0)      scale = 25.f / (2.f * 2097152.f);
        else if (s == 1) scale = 25.f / (4.f * 131072.f);
        else             scale = 1.f / (225.f * 524288.f);
        out[s] = tot * scale;
    }
}

// ---------------- launch ----------------
extern "C" void kernel_launch(void* const* d_in, const int* in_sizes, int n_in,
                              void* d_out, int out_size) {
    const float* e1 = (const float*)d_in[0];
    const float* e2 = (const float*)d_in[1];
    float* out = (float*)d_out;
    (void)in_sizes; (void)n_in; (void)out_size;

    cudaFuncSetAttribute(k_dots, cudaFuncAttributeMaxDynamicSharedMemorySize, SM_DOTS);

    k_prep<<<dim3(32, 16), dim3(32, 8)>>>(e1, e2);
    k_dots<<<dim3(8, 16), 512, SM_DOTS>>>();
    k_stats<<<dim3(MM, 2), 128>>>();
    k_final<<<3, 1024>>>(out);
}

// round 8
// speedup vs baseline: 4.3507x; 1.1540x over previous
#include <cuda_runtime.h>
#include <cuda_bf16.h>
#include <stdint.h>

#define BB 16
#define MM 1024
#define CC 128
#define BM (BB*MM)

// ---------------- device scratch ----------------
__device__ float g_n1[BM];
__device__ float g_n2[BM];
__device__ unsigned long long g_idx1p[BM];
__device__ unsigned long long g_idx2p[BM];
__device__ float g_part[3][2048];
__device__ __nv_bfloat16 g_hl1[(size_t)BM * 256];  // rows [hi(128)|lo(128)]
__device__ __nv_bfloat16 g_hl2[(size_t)BM * 256];
__device__ int g_done;

// ---------------- helpers ----------------
__device__ __forceinline__ uint32_t smem_u32(const void* p) {
    uint32_t a;
    asm("{ .reg .u64 t; cvta.to.shared.u64 t, %1; cvt.u32.u64 %0, t; }" : "=r"(a) : "l"(p));
    return a;
}
__device__ __forceinline__ unsigned int fenc(float f) {
    unsigned int u = __float_as_uint(f);
    return (u & 0x80000000u) ? ~u : (u | 0x80000000u);
}
__device__ __forceinline__ void cpa16(uint32_t dst, const void* src) {
    asm volatile("cp.async.cg.shared.global [%0], [%1], 16;" :: "r"(dst), "l"(src));
}
#define CP_COMMIT() asm volatile("cp.async.commit_group;" ::: "memory")
#define CP_WAIT(n)  asm volatile("cp.async.wait_group %0;" :: "n"(n) : "memory")

#define LDMX4(r0, r1, r2, r3, addr) \
    asm volatile("ldmatrix.sync.aligned.m8n8.x4.shared.b16 {%0,%1,%2,%3}, [%4];" \
        : "=r"(r0), "=r"(r1), "=r"(r2), "=r"(r3) : "r"(addr))

#define MMA16816(d, a0, a1, a2, a3, b0, b1) \
    asm volatile("mma.sync.aligned.m16n8k16.row.col.f32.bf16.bf16.f32 " \
        "{%0,%1,%2,%3}, {%4,%5,%6,%7}, {%8,%9}, {%0,%1,%2,%3};" \
        : "+f"((d)[0]), "+f"((d)[1]), "+f"((d)[2]), "+f"((d)[3]) \
        : "r"(a0), "r"(a1), "r"(a2), "r"(a3), "r"(b0), "r"(b1))

// ---------------- K1: fused transpose + bf16 hi/lo + norms + idx init ----------------
__global__ void __launch_bounds__(256) k_prep(const float* __restrict__ e1,
                                              const float* __restrict__ e2) {
    __shared__ float sm[2][32][33];
    int b = blockIdx.y;
    int i0 = blockIdx.x * 32;
    int tx = threadIdx.x, ty = threadIdx.y;
    const float* s1 = e1 + (size_t)b * CC * MM;
    const float* s2 = e2 + (size_t)b * CC * MM;

    if (ty == 0) {
        g_idx1p[b * MM + i0 + tx] = ~0ULL;
        g_idx2p[b * MM + i0 + tx] = ~0ULL;
    }
    if (blockIdx.x == 0 && blockIdx.y == 0 && tx == 0 && ty == 0) g_done = 0;

    float ns1[4] = {0.f, 0.f, 0.f, 0.f};
    float ns2[4] = {0.f, 0.f, 0.f, 0.f};

#pragma unroll 1
    for (int cc = 0; cc < 4; cc++) {
        __syncthreads();
#pragma unroll
        for (int q = 0; q < 4; q++) {
            int c = cc * 32 + ty + q * 8;
            sm[0][ty + q * 8][tx] = s1[(size_t)c * MM + i0 + tx];
            sm[1][ty + q * 8][tx] = s2[(size_t)c * MM + i0 + tx];
        }
        __syncthreads();
#pragma unroll
        for (int q = 0; q < 4; q++) {
            int i = i0 + ty + q * 8;
            size_t row = (size_t)b * MM + i;
            int c = cc * 32 + tx;
            float v1 = sm[0][tx][ty + q * 8];
            float v2 = sm[1][tx][ty + q * 8];
            __nv_bfloat16 h1 = __float2bfloat16(v1);
            __nv_bfloat16 h2 = __float2bfloat16(v2);
            g_hl1[row * 256 + c]       = h1;
            g_hl1[row * 256 + 128 + c] = __float2bfloat16(v1 - __bfloat162float(h1));
            g_hl2[row * 256 + c]       = h2;
            g_hl2[row * 256 + 128 + c] = __float2bfloat16(v2 - __bfloat162float(h2));
            ns1[q] = fmaf(v1, v1, ns1[q]);
            ns2[q] = fmaf(v2, v2, ns2[q]);
        }
    }

#pragma unroll
    for (int q = 0; q < 4; q++) {
        float s1v = ns1[q], s2v = ns2[q];
#pragma unroll
        for (int off = 16; off >= 1; off >>= 1) {
            s1v += __shfl_down_sync(0xFFFFFFFFu, s1v, off);
            s2v += __shfl_down_sync(0xFFFFFFFFu, s2v, off);
        }
        if (tx == 0) {
            g_n1[b * MM + i0 + ty + q * 8] = s1v;
            g_n2[b * MM + i0 + ty + q * 8] = s2v;
        }
    }
}

// ---------------- K2: pure-hi bf16 mma GEMM + dual argmin (16 warps) ----------------
// dot ~= Ahi*Bhi  (norms exact fp32; d2 error ~0.07, flips perturb stats ~1e-5)
#define ROWA 272
#define SM_A_SZ (128 * ROWA)                    // 34816
#define SM_SCOL (SM_A_SZ + 2 * 128 * ROWA)      // 104448
#define SM_DOTS (SM_SCOL + 8192)                // 112640

__global__ void __launch_bounds__(512, 1) k_dots() {
    extern __shared__ char smem[];
    uint32_t sb = smem_u32(smem);
    const uint32_t SA = sb;
    const uint32_t SB0 = sb + SM_A_SZ;
    unsigned long long* scol = (unsigned long long*)(smem + SM_SCOL);
    int tid = threadIdx.x, wid = tid >> 5, l = tid & 31;
    int b = blockIdx.y;
    int i0 = blockIdx.x * 128;
    const char* Ag = (const char*)(g_hl1 + ((size_t)(b * MM + i0)) * 256);
    const char* Bg = (const char*)(g_hl2 + ((size_t)b * MM) * 256);

    // prologue: A-hi + B0-hi (256B useful per 512B row)
#pragma unroll
    for (int q = 0; q < 4; q++) {
        int ch = tid + q * 512;           // 2048 chunks: 128 rows x 16
        int row = ch >> 4, c16 = ch & 15;
        cpa16(SA + row * ROWA + c16 * 16, Ag + row * 512 + c16 * 16);
    }
#pragma unroll
    for (int q = 0; q < 4; q++) {
        int ch = tid + q * 512;
        int row = ch >> 4, c16 = ch & 15;
        cpa16(SB0 + row * ROWA + c16 * 16, Bg + row * 512 + c16 * 16);
    }
    CP_COMMIT();

    for (int v = tid; v < 1024; v += 512) scol[v] = ~0ULL;

    int wy = wid >> 2, wx = wid & 3;
    int m0w = wy * 32, n0w = wx * 32;

    int rowA = (l & 7) + ((l >> 3) & 1) * 8;
    int koffA = (l >> 4) * 8;
    uint32_t aBase = SA + (uint32_t)(m0w + rowA) * ROWA + koffA * 2;
    int rowB = (l & 7) + ((l >> 4) & 1) * 8;
    int koffB = ((l >> 3) & 1) * 8;
    uint32_t bLane = (uint32_t)(n0w + rowB) * ROWA + koffB * 2;

    float n1r[2][2];
#pragma unroll
    for (int mf = 0; mf < 2; mf++)
#pragma unroll
        for (int h = 0; h < 2; h++)
            n1r[mf][h] = g_n1[b * MM + i0 + m0w + mf * 16 + (l >> 2) + h * 8];

    unsigned long long run1[2][2];
    run1[0][0] = ~0ULL; run1[0][1] = ~0ULL; run1[1][0] = ~0ULL; run1[1][1] = ~0ULL;

#pragma unroll 1
    for (int jt = 0; jt < 8; jt++) {
        int j0 = jt * 128;
        __syncthreads();
        if (jt < 7) {
            const char* src = Bg + (size_t)(jt + 1) * 128 * 512;
            uint32_t dstb = SB0 + (uint32_t)((jt + 1) & 1) * 128 * ROWA;
#pragma unroll
            for (int q = 0; q < 4; q++) {
                int ch = tid + q * 512;
                int row = ch >> 4, c16 = ch & 15;
                cpa16(dstb + row * ROWA + c16 * 16, src + row * 512 + c16 * 16);
            }
            CP_COMMIT();
            CP_WAIT(1);
        } else {
            CP_WAIT(0);
        }
        __syncthreads();

        uint32_t bBase = SB0 + (uint32_t)(jt & 1) * 128 * ROWA + bLane;

        float acc[2][4][4];
#pragma unroll
        for (int mf = 0; mf < 2; mf++)
#pragma unroll
            for (int nf = 0; nf < 4; nf++)
#pragma unroll
                for (int r = 0; r < 4; r++) acc[mf][nf][r] = 0.f;

#pragma unroll
        for (int ks = 0; ks < 8; ks++) {
            uint32_t ao = (uint32_t)ks * 32u;
            uint32_t ahi[2][4], bhi[2][4];
#pragma unroll
            for (int mf = 0; mf < 2; mf++)
                LDMX4(ahi[mf][0], ahi[mf][1], ahi[mf][2], ahi[mf][3],
                      aBase + (uint32_t)mf * 16 * ROWA + ao);
#pragma unroll
            for (int np = 0; np < 2; np++)
                LDMX4(bhi[np][0], bhi[np][1], bhi[np][2], bhi[np][3],
                      bBase + (uint32_t)np * 16 * ROWA + ao);
#pragma unroll
            for (int mf = 0; mf < 2; mf++)
#pragma unroll
                for (int np = 0; np < 2; np++) {
                    MMA16816(acc[mf][np * 2],     ahi[mf][0], ahi[mf][1], ahi[mf][2], ahi[mf][3], bhi[np][0], bhi[np][1]);
                    MMA16816(acc[mf][np * 2 + 1], ahi[mf][0], ahi[mf][1], ahi[mf][2], ahi[mf][3], bhi[np][2], bhi[np][3]);
                }
        }

        // ---- epilogue ----
        float n2r[4][2];
#pragma unroll
        for (int nf = 0; nf < 4; nf++)
#pragma unroll
            for (int p = 0; p < 2; p++)
                n2r[nf][p] = g_n2[b * MM + j0 + n0w + nf * 8 + (l & 3) * 2 + p];

        // row minima: per-lane running min (shfl-combine deferred)
#pragma unroll
        for (int mf = 0; mf < 2; mf++)
#pragma unroll
            for (int h = 0; h < 2; h++) {
#pragma unroll
                for (int nf = 0; nf < 4; nf++)
#pragma unroll
                    for (int p = 0; p < 2; p++) {
                        float val = fmaf(-2.f, acc[mf][nf][h * 2 + p], n2r[nf][p]);
                        int j = j0 + n0w + nf * 8 + (l & 3) * 2 + p;
                        unsigned long long e =
                            ((unsigned long long)fenc(val) << 32) | (unsigned)j;
                        if (e < run1[mf][h]) run1[mf][h] = e;
                    }
            }

        // col minima -> shared accumulation
#pragma unroll
        for (int nf = 0; nf < 4; nf++)
#pragma unroll
            for (int p = 0; p < 2; p++) {
                unsigned long long pk = ~0ULL;
#pragma unroll
                for (int mf = 0; mf < 2; mf++)
#pragma unroll
                    for (int h = 0; h < 2; h++) {
                        float val = fmaf(-2.f, acc[mf][nf][h * 2 + p], n1r[mf][h]);
                        int i = i0 + m0w + mf * 16 + (l >> 2) + h * 8;
                        unsigned long long e =
                            ((unsigned long long)fenc(val) << 32) | (unsigned)i;
                        if (e < pk) pk = e;
                    }
                unsigned long long o;
                o = __shfl_xor_sync(0xFFFFFFFFu, pk, 4);  if (o < pk) pk = o;
                o = __shfl_xor_sync(0xFFFFFFFFu, pk, 8);  if (o < pk) pk = o;
                o = __shfl_xor_sync(0xFFFFFFFFu, pk, 16); if (o < pk) pk = o;
                if (l < 4)
                    atomicMin(&scol[j0 + n0w + nf * 8 + (l & 3) * 2 + p], pk);
            }
    }

    // flush row minima
#pragma unroll
    for (int mf = 0; mf < 2; mf++)
#pragma unroll
        for (int h = 0; h < 2; h++) {
            unsigned long long r = run1[mf][h], o;
            o = __shfl_xor_sync(0xFFFFFFFFu, r, 1); if (o < r) r = o;
            o = __shfl_xor_sync(0xFFFFFFFFu, r, 2); if (o < r) r = o;
            if ((l & 3) == 0)
                atomicMin(&g_idx1p[b * MM + i0 + m0w + mf * 16 + (l >> 2) + h * 8], r);
        }

    // flush col minima
    __syncthreads();
    for (int v = tid; v < 1024; v += 512)
        atomicMin(&g_idx2p[b * MM + v], scol[v]);
}

// ---------------- K3: gather NN + vicreg stats + fused final reduction ----------------
__global__ void __launch_bounds__(128) k_stats(float* __restrict__ out) {
    __shared__ __align__(16) __nv_bfloat16 Xb[2][16][136];  // row stride 272B
    __shared__ float sred[12];
    __shared__ int amLast;
    int i = blockIdx.x;
    int p = blockIdx.y;
    int c = threadIdx.x;
    const __nv_bfloat16* tx_ = p ? g_hl2 : g_hl1;
    const __nv_bfloat16* ty_ = p ? g_hl1 : g_hl2;

    float x[16], y[16];
#pragma unroll
    for (int b = 0; b < 16; b++) {
        int j = (int)((p ? g_idx2p[b * MM + i] : g_idx1p[b * MM + i]) & 0xFFFFFFFFULL);
        size_t rx = ((size_t)b * MM + i) * 256;
        size_t ry = ((size_t)b * MM + j) * 256;
        x[b] = __bfloat162float(tx_[rx + c]) + __bfloat162float(tx_[rx + 128 + c]);
        y[b] = __bfloat162float(ty_[ry + c]) + __bfloat162float(ty_[ry + 128 + c]);
    }

    float repr = 0.f;
#pragma unroll
    for (int b = 0; b < 16; b++) { float d = x[b] - y[b]; repr += d * d; }

    float mux = 0.f, muy = 0.f;
#pragma unroll
    for (int b = 0; b < 16; b++) { mux += x[b]; muy += y[b]; }
    mux *= (1.f / 16.f); muy *= (1.f / 16.f);

    float sx = 0.f, sy = 0.f;
#pragma unroll
    for (int b = 0; b < 16; b++) {
        x[b] -= mux; sx += x[b] * x[b];
        y[b] -= muy; sy += y[b] * y[b];
    }
    float stdp = fmaxf(0.f, 1.f - sqrtf(sx * (1.f / 15.f) + 1e-4f))
               + fmaxf(0.f, 1.f - sqrtf(sy * (1.f / 15.f) + 1e-4f));
    float S2 = sx * sx + sy * sy;

#pragma unroll
    for (int b = 0; b < 16; b++) {
        Xb[0][b][c] = __float2bfloat16(x[b]);
        Xb[1][b][c] = __float2bfloat16(y[b]);
    }
    __syncthreads();

    float covpart = -S2;
    int wid = c >> 5, l = c & 31;
    if (wid < 2) {
        int t = wid;
        int rowA = (l & 7) + ((l >> 3) & 1) * 8;
        int koffA = (l >> 4) * 8;
        int rowB = (l & 7) + ((l >> 4) & 1) * 8;
        int koffB = ((l >> 3) & 1) * 8;
        uint32_t tb = smem_u32(&Xb[0][0][0]) + (uint32_t)t * 16 * 272;
        uint32_t aB = tb + (uint32_t)rowA * 272 + koffA * 2;
        uint32_t bB = tb + (uint32_t)rowB * 272 + koffB * 2;
        float acc[8];
#pragma unroll
        for (int r = 0; r < 8; r++) acc[r] = 0.f;
#pragma unroll
        for (int ks = 0; ks < 8; ks++) {
            uint32_t a0, a1, a2, a3, b0, b1, b2, b3;
            LDMX4(a0, a1, a2, a3, aB + ks * 32);
            LDMX4(b0, b1, b2, b3, bB + ks * 32);
            MMA16816(acc,     a0, a1, a2, a3, b0, b1);
            MMA16816(acc + 4, a0, a1, a2, a3, b2, b3);
        }
#pragma unroll
        for (int r = 0; r < 8; r++)
            covpart = fmaf(acc[r], acc[r], covpart);
    }

    float v0 = repr, v1 = stdp, v2 = covpart;
#pragma unroll
    for (int off = 16; off >= 1; off >>= 1) {
        v0 += __shfl_down_sync(0xFFFFFFFFu, v0, off);
        v1 += __shfl_down_sync(0xFFFFFFFFu, v1, off);
        v2 += __shfl_down_sync(0xFFFFFFFFu, v2, off);
    }
    if ((c & 31) == 0) { sred[wid] = v0; sred[4 + wid] = v1; sred[8 + wid] = v2; }
    __syncthreads();
    if (c == 0) {
        int blk = p * 1024 + i;
        g_part[0][blk] = sred[0] + sred[1] + sred[2] + sred[3];
        g_part[1][blk] = sred[4] + sred[5] + sred[6] + sred[7];
        g_part[2][blk] = sred[8] + sred[9] + sred[10] + sred[11];
        __threadfence();
        amLast = (atomicAdd(&g_done, 1) == 2047);
    }
    __syncthreads();

    if (amLast) {
        // last block: deterministic final reduction of 3 x 2048 partials
        __shared__ float fred[3][4];
#pragma unroll 1
        for (int s = 0; s < 3; s++) {
            float v = 0.f;
            for (int k = c; k < 2048; k += 128) v += g_part[s][k];
#pragma unroll
            for (int off = 16; off >= 1; off >>= 1)
                v += __shfl_down_sync(0xFFFFFFFFu, v, off);
            if ((c & 31) == 0) fred[s][c >> 5] = v;
        }
        __syncthreads();
        if (c < 3) {
            float tot = fred[c][0] + fred[c][1] + fred[c][2] + fred[c][3];
            float scale;
            if (c == 0)      scale = 25.f / (2.f * 2097152.f);
            else if (c == 1) scale = 25.f / (4.f * 131072.f);
            else             scale = 1.f / (225.f * 524288.f);
            out[c] = tot * scale;
        }
    }
}

// ---------------- launch ----------------
extern "C" void kernel_launch(void* const* d_in, const int* in_sizes, int n_in,
                              void* d_out, int out_size) {
    const float* e1 = (const float*)d_in[0];
    const float* e2 = (const float*)d_in[1];
    float* out = (float*)d_out;
    (void)in_sizes; (void)n_in; (void)out_size;

    cudaFuncSetAttribute(k_dots, cudaFuncAttributeMaxDynamicSharedMemorySize, SM_DOTS);

    k_prep<<<dim3(32, 16), dim3(32, 8)>>>(e1, e2);
    k_dots<<<dim3(8, 16), 512, SM_DOTS>>>();
    k_stats<<<dim3(MM, 2), 128>>>(out);
}

// round 9
// speedup vs baseline: 4.4252x; 1.0171x over previous
#include <cuda_runtime.h>
#include <cuda_bf16.h>
#include <stdint.h>

#define BB 16
#define MM 1024
#define CC 128
#define BM (BB*MM)

// ---------------- device scratch ----------------
__device__ float g_n1[BM];
__device__ float g_n2[BM];
__device__ unsigned long long g_idx1p[BM];
__device__ unsigned long long g_idx2p[BM];
__device__ float g_part[3][2048];
__device__ __nv_bfloat16 g_h1[(size_t)BM * 128];   // bf16(hi) rows, 256B each
__device__ __nv_bfloat16 g_h2[(size_t)BM * 128];
__device__ int g_done;

// ---------------- helpers ----------------
__device__ __forceinline__ uint32_t smem_u32(const void* p) {
    uint32_t a;
    asm("{ .reg .u64 t; cvta.to.shared.u64 t, %1; cvt.u32.u64 %0, t; }" : "=r"(a) : "l"(p));
    return a;
}
__device__ __forceinline__ unsigned int fenc(float f) {
    unsigned int u = __float_as_uint(f);
    return (u & 0x80000000u) ? ~u : (u | 0x80000000u);
}
__device__ __forceinline__ void cpa16(uint32_t dst, const void* src) {
    asm volatile("cp.async.cg.shared.global [%0], [%1], 16;" :: "r"(dst), "l"(src));
}
#define CP_COMMIT() asm volatile("cp.async.commit_group;" ::: "memory")
#define CP_WAIT(n)  asm volatile("cp.async.wait_group %0;" :: "n"(n) : "memory")

#define LDMX4(r0, r1, r2, r3, addr) \
    asm volatile("ldmatrix.sync.aligned.m8n8.x4.shared.b16 {%0,%1,%2,%3}, [%4];" \
        : "=r"(r0), "=r"(r1), "=r"(r2), "=r"(r3) : "r"(addr))

#define MMA16816(d, a0, a1, a2, a3, b0, b1) \
    asm volatile("mma.sync.aligned.m16n8k16.row.col.f32.bf16.bf16.f32 " \
        "{%0,%1,%2,%3}, {%4,%5,%6,%7}, {%8,%9}, {%0,%1,%2,%3};" \
        : "+f"((d)[0]), "+f"((d)[1]), "+f"((d)[2]), "+f"((d)[3]) \
        : "r"(a0), "r"(a1), "r"(a2), "r"(a3), "r"(b0), "r"(b1))

// ---------------- K1: fused transpose + bf16 + norms + idx init ----------------
__global__ void __launch_bounds__(256) k_prep(const float* __restrict__ e1,
                                              const float* __restrict__ e2) {
    __shared__ float sm[2][32][33];
    int b = blockIdx.y;
    int i0 = blockIdx.x * 32;
    int tx = threadIdx.x, ty = threadIdx.y;
    const float* s1 = e1 + (size_t)b * CC * MM;
    const float* s2 = e2 + (size_t)b * CC * MM;

    if (ty == 0) {
        g_idx1p[b * MM + i0 + tx] = ~0ULL;
        g_idx2p[b * MM + i0 + tx] = ~0ULL;
    }
    if (blockIdx.x == 0 && blockIdx.y == 0 && tx == 0 && ty == 0) g_done = 0;

    float ns1[4] = {0.f, 0.f, 0.f, 0.f};
    float ns2[4] = {0.f, 0.f, 0.f, 0.f};

#pragma unroll 1
    for (int cc = 0; cc < 4; cc++) {
        __syncthreads();
#pragma unroll
        for (int q = 0; q < 4; q++) {
            int c = cc * 32 + ty + q * 8;
            sm[0][ty + q * 8][tx] = s1[(size_t)c * MM + i0 + tx];
            sm[1][ty + q * 8][tx] = s2[(size_t)c * MM + i0 + tx];
        }
        __syncthreads();
#pragma unroll
        for (int q = 0; q < 4; q++) {
            int i = i0 + ty + q * 8;
            size_t row = (size_t)b * MM + i;
            int c = cc * 32 + tx;
            float v1 = sm[0][tx][ty + q * 8];
            float v2 = sm[1][tx][ty + q * 8];
            g_h1[row * 128 + c] = __float2bfloat16(v1);
            g_h2[row * 128 + c] = __float2bfloat16(v2);
            ns1[q] = fmaf(v1, v1, ns1[q]);
            ns2[q] = fmaf(v2, v2, ns2[q]);
        }
    }

#pragma unroll
    for (int q = 0; q < 4; q++) {
        float s1v = ns1[q], s2v = ns2[q];
#pragma unroll
        for (int off = 16; off >= 1; off >>= 1) {
            s1v += __shfl_down_sync(0xFFFFFFFFu, s1v, off);
            s2v += __shfl_down_sync(0xFFFFFFFFu, s2v, off);
        }
        if (tx == 0) {
            g_n1[b * MM + i0 + ty + q * 8] = s1v;
            g_n2[b * MM + i0 + ty + q * 8] = s2v;
        }
    }
}

// ---------------- K2: pure-bf16 mma GEMM + dual argmin (16 warps) ----------------
#define ROWA 272
#define SM_A_SZ (128 * ROWA)                    // 34816
#define SM_SCOL (SM_A_SZ + 2 * 128 * ROWA)      // 104448
#define SM_DOTS (SM_SCOL + 8192)                // 112640

__global__ void __launch_bounds__(512, 1) k_dots() {
    extern __shared__ char smem[];
    uint32_t sb = smem_u32(smem);
    const uint32_t SA = sb;
    const uint32_t SB0 = sb + SM_A_SZ;
    unsigned long long* scol = (unsigned long long*)(smem + SM_SCOL);
    int tid = threadIdx.x, wid = tid >> 5, l = tid & 31;
    int b = blockIdx.y;
    int i0 = blockIdx.x * 128;
    const char* Ag = (const char*)(g_h1 + ((size_t)(b * MM + i0)) * 128);
    const char* Bg = (const char*)(g_h2 + ((size_t)b * MM) * 128);

    // prologue: A + B0 (dense 256B rows)
#pragma unroll
    for (int q = 0; q < 4; q++) {
        int ch = tid + q * 512;           // 2048 chunks: 128 rows x 16
        int row = ch >> 4, c16 = ch & 15;
        cpa16(SA + row * ROWA + c16 * 16, Ag + row * 256 + c16 * 16);
    }
#pragma unroll
    for (int q = 0; q < 4; q++) {
        int ch = tid + q * 512;
        int row = ch >> 4, c16 = ch & 15;
        cpa16(SB0 + row * ROWA + c16 * 16, Bg + row * 256 + c16 * 16);
    }
    CP_COMMIT();

    for (int v = tid; v < 1024; v += 512) scol[v] = ~0ULL;

    int wy = wid >> 2, wx = wid & 3;
    int m0w = wy * 32, n0w = wx * 32;

    int rowA = (l & 7) + ((l >> 3) & 1) * 8;
    int koffA = (l >> 4) * 8;
    uint32_t aBase = SA + (uint32_t)(m0w + rowA) * ROWA + koffA * 2;
    int rowB = (l & 7) + ((l >> 4) & 1) * 8;
    int koffB = ((l >> 3) & 1) * 8;
    uint32_t bLane = (uint32_t)(n0w + rowB) * ROWA + koffB * 2;

    float n1r[2][2];
#pragma unroll
    for (int mf = 0; mf < 2; mf++)
#pragma unroll
        for (int h = 0; h < 2; h++)
            n1r[mf][h] = g_n1[b * MM + i0 + m0w + mf * 16 + (l >> 2) + h * 8];

    unsigned long long run1[2][2];
    run1[0][0] = ~0ULL; run1[0][1] = ~0ULL; run1[1][0] = ~0ULL; run1[1][1] = ~0ULL;

#pragma unroll 1
    for (int jt = 0; jt < 8; jt++) {
        int j0 = jt * 128;
        __syncthreads();
        if (jt < 7) {
            const char* src = Bg + (size_t)(jt + 1) * 128 * 256;
            uint32_t dstb = SB0 + (uint32_t)((jt + 1) & 1) * 128 * ROWA;
#pragma unroll
            for (int q = 0; q < 4; q++) {
                int ch = tid + q * 512;
                int row = ch >> 4, c16 = ch & 15;
                cpa16(dstb + row * ROWA + c16 * 16, src + row * 256 + c16 * 16);
            }
            CP_COMMIT();
            CP_WAIT(1);
        } else {
            CP_WAIT(0);
        }
        __syncthreads();

        uint32_t bBase = SB0 + (uint32_t)(jt & 1) * 128 * ROWA + bLane;

        float acc[2][4][4];
#pragma unroll
        for (int mf = 0; mf < 2; mf++)
#pragma unroll
            for (int nf = 0; nf < 4; nf++)
#pragma unroll
                for (int r = 0; r < 4; r++) acc[mf][nf][r] = 0.f;

#pragma unroll
        for (int ks = 0; ks < 8; ks++) {
            uint32_t ao = (uint32_t)ks * 32u;
            uint32_t ahi[2][4], bhi[2][4];
#pragma unroll
            for (int mf = 0; mf < 2; mf++)
                LDMX4(ahi[mf][0], ahi[mf][1], ahi[mf][2], ahi[mf][3],
                      aBase + (uint32_t)mf * 16 * ROWA + ao);
#pragma unroll
            for (int np = 0; np < 2; np++)
                LDMX4(bhi[np][0], bhi[np][1], bhi[np][2], bhi[np][3],
                      bBase + (uint32_t)np * 16 * ROWA + ao);
#pragma unroll
            for (int mf = 0; mf < 2; mf++)
#pragma unroll
                for (int np = 0; np < 2; np++) {
                    MMA16816(acc[mf][np * 2],     ahi[mf][0], ahi[mf][1], ahi[mf][2], ahi[mf][3], bhi[np][0], bhi[np][1]);
                    MMA16816(acc[mf][np * 2 + 1], ahi[mf][0], ahi[mf][1], ahi[mf][2], ahi[mf][3], bhi[np][2], bhi[np][3]);
                }
        }

        // ---- epilogue ----
        float n2r[4][2];
#pragma unroll
        for (int nf = 0; nf < 4; nf++)
#pragma unroll
            for (int p = 0; p < 2; p++)
                n2r[nf][p] = g_n2[b * MM + j0 + n0w + nf * 8 + (l & 3) * 2 + p];

#pragma unroll
        for (int mf = 0; mf < 2; mf++)
#pragma unroll
            for (int h = 0; h < 2; h++) {
#pragma unroll
                for (int nf = 0; nf < 4; nf++)
#pragma unroll
                    for (int p = 0; p < 2; p++) {
                        float val = fmaf(-2.f, acc[mf][nf][h * 2 + p], n2r[nf][p]);
                        int j = j0 + n0w + nf * 8 + (l & 3) * 2 + p;
                        unsigned long long e =
                            ((unsigned long long)fenc(val) << 32) | (unsigned)j;
                        if (e < run1[mf][h]) run1[mf][h] = e;
                    }
            }

#pragma unroll
        for (int nf = 0; nf < 4; nf++)
#pragma unroll
            for (int p = 0; p < 2; p++) {
                unsigned long long pk = ~0ULL;
#pragma unroll
                for (int mf = 0; mf < 2; mf++)
#pragma unroll
                    for (int h = 0; h < 2; h++) {
                        float val = fmaf(-2.f, acc[mf][nf][h * 2 + p], n1r[mf][h]);
                        int i = i0 + m0w + mf * 16 + (l >> 2) + h * 8;
                        unsigned long long e =
                            ((unsigned long long)fenc(val) << 32) | (unsigned)i;
                        if (e < pk) pk = e;
                    }
                unsigned long long o;
                o = __shfl_xor_sync(0xFFFFFFFFu, pk, 4);  if (o < pk) pk = o;
                o = __shfl_xor_sync(0xFFFFFFFFu, pk, 8);  if (o < pk) pk = o;
                o = __shfl_xor_sync(0xFFFFFFFFu, pk, 16); if (o < pk) pk = o;
                if (l < 4)
                    atomicMin(&scol[j0 + n0w + nf * 8 + (l & 3) * 2 + p], pk);
            }
    }

    // flush row minima
#pragma unroll
    for (int mf = 0; mf < 2; mf++)
#pragma unroll
        for (int h = 0; h < 2; h++) {
            unsigned long long r = run1[mf][h], o;
            o = __shfl_xor_sync(0xFFFFFFFFu, r, 1); if (o < r) r = o;
            o = __shfl_xor_sync(0xFFFFFFFFu, r, 2); if (o < r) r = o;
            if ((l & 3) == 0)
                atomicMin(&g_idx1p[b * MM + i0 + m0w + mf * 16 + (l >> 2) + h * 8], r);
        }

    __syncthreads();
    for (int v = tid; v < 1024; v += 512)
        atomicMin(&g_idx2p[b * MM + v], scol[v]);
}

// ---------------- K3: staged gather + vicreg stats + fused final ----------------
__global__ void __launch_bounds__(128) k_stats(float* __restrict__ out) {
    __shared__ __align__(16) uint32_t Raw[2][16][66];       // 32 rows x 64 u32 (+2 pad)
    __shared__ __align__(16) __nv_bfloat16 Xb[2][16][136];  // centered, 272B stride
    __shared__ float sred[12];
    __shared__ int sidx[16];
    __shared__ int amLast;
    int i = blockIdx.x;
    int p = blockIdx.y;
    int c = threadIdx.x;
    const __nv_bfloat16* tx_ = p ? g_h2 : g_h1;
    const __nv_bfloat16* ty_ = p ? g_h1 : g_h2;

    if (c < 16)
        sidx[c] = (int)((p ? g_idx2p[c * MM + i] : g_idx1p[c * MM + i]) & 0xFFFFFFFFULL);
    __syncthreads();

    // coalesced stage: 32 rows x 64 u32 (x rows + gathered y rows)
#pragma unroll
    for (int q = 0; q < 16; q++) {
        int t = c + q * 128;
        int half = t >> 10;
        int b = (t >> 6) & 15;
        int w = t & 63;
        const __nv_bfloat16* src = half ? (ty_ + ((size_t)b * MM + sidx[b]) * 128)
                                        : (tx_ + ((size_t)b * MM + i) * 128);
        Raw[half][b][w] = ((const uint32_t*)src)[w];
    }
    __syncthreads();

    float x[16], y[16];
#pragma unroll
    for (int b = 0; b < 16; b++) {
        x[b] = __bfloat162float(((const __nv_bfloat16*)&Raw[0][b][0])[c]);
        y[b] = __bfloat162float(((const __nv_bfloat16*)&Raw[1][b][0])[c]);
    }

    float repr = 0.f;
#pragma unroll
    for (int b = 0; b < 16; b++) { float d = x[b] - y[b]; repr += d * d; }

    float mux = 0.f, muy = 0.f;
#pragma unroll
    for (int b = 0; b < 16; b++) { mux += x[b]; muy += y[b]; }
    mux *= (1.f / 16.f); muy *= (1.f / 16.f);

    float sx = 0.f, sy = 0.f;
#pragma unroll
    for (int b = 0; b < 16; b++) {
        x[b] -= mux; sx += x[b] * x[b];
        y[b] -= muy; sy += y[b] * y[b];
    }
    float stdp = fmaxf(0.f, 1.f - sqrtf(sx * (1.f / 15.f) + 1e-4f))
               + fmaxf(0.f, 1.f - sqrtf(sy * (1.f / 15.f) + 1e-4f));
    float S2 = sx * sx + sy * sy;

#pragma unroll
    for (int b = 0; b < 16; b++) {
        Xb[0][b][c] = __float2bfloat16(x[b]);
        Xb[1][b][c] = __float2bfloat16(y[b]);
    }
    __syncthreads();

    float covpart = -S2;
    int wid = c >> 5, l = c & 31;
    if (wid < 2) {
        int t = wid;
        int rowA = (l & 7) + ((l >> 3) & 1) * 8;
        int koffA = (l >> 4) * 8;
        int rowB = (l & 7) + ((l >> 4) & 1) * 8;
        int koffB = ((l >> 3) & 1) * 8;
        uint32_t tb = smem_u32(&Xb[0][0][0]) + (uint32_t)t * 16 * 272;
        uint32_t aB = tb + (uint32_t)rowA * 272 + koffA * 2;
        uint32_t bB = tb + (uint32_t)rowB * 272 + koffB * 2;
        float acc[8];
#pragma unroll
        for (int r = 0; r < 8; r++) acc[r] = 0.f;
#pragma unroll
        for (int ks = 0; ks < 8; ks++) {
            uint32_t a0, a1, a2, a3, b0, b1, b2, b3;
            LDMX4(a0, a1, a2, a3, aB + ks * 32);
            LDMX4(b0, b1, b2, b3, bB + ks * 32);
            MMA16816(acc,     a0, a1, a2, a3, b0, b1);
            MMA16816(acc + 4, a0, a1, a2, a3, b2, b3);
        }
#pragma unroll
        for (int r = 0; r < 8; r++)
            covpart = fmaf(acc[r], acc[r], covpart);
    }

    float v0 = repr, v1 = stdp, v2 = covpart;
#pragma unroll
    for (int off = 16; off >= 1; off >>= 1) {
        v0 += __shfl_down_sync(0xFFFFFFFFu, v0, off);
        v1 += __shfl_down_sync(0xFFFFFFFFu, v1, off);
        v2 += __shfl_down_sync(0xFFFFFFFFu, v2, off);
    }
    if ((c & 31) == 0) { sred[wid] = v0; sred[4 + wid] = v1; sred[8 + wid] = v2; }
    __syncthreads();
    if (c == 0) {
        int blk = p * 1024 + i;
        g_part[0][blk] = sred[0] + sred[1] + sred[2] + sred[3];
        g_part[1][blk] = sred[4] + sred[5] + sred[6] + sred[7];
        g_part[2][blk] = sred[8] + sred[9] + sred[10] + sred[11];
        __threadfence();
        amLast = (atomicAdd(&g_done, 1) == 2047);
    }
    __syncthreads();

    if (amLast) {
        __shared__ float fred[3][4];
#pragma unroll 1
        for (int s = 0; s < 3; s++) {
            float v = 0.f;
            for (int k = c; k < 2048; k += 128) v += g_part[s][k];
#pragma unroll
            for (int off = 16; off >= 1; off >>= 1)
                v += __shfl_down_sync(0xFFFFFFFFu, v, off);
            if ((c & 31) == 0) fred[s][c >> 5] = v;
        }
        __syncthreads();
        if (c < 3) {
            float tot = fred[c][0] + fred[c][1] + fred[c][2] + fred[c][3];
            float scale;
            if (c == 0)      scale = 25.f / (2.f * 2097152.f);
            else if (c == 1) scale = 25.f / (4.f * 131072.f);
            else             scale = 1.f / (225.f * 524288.f);
            out[c] = tot * scale;
        }
    }
}

// ---------------- launch ----------------
extern "C" void kernel_launch(void* const* d_in, const int* in_sizes, int n_in,
                              void* d_out, int out_size) {
    const float* e1 = (const float*)d_in[0];
    const float* e2 = (const float*)d_in[1];
    float* out = (float*)d_out;
    (void)in_sizes; (void)n_in; (void)out_size;

    cudaFuncSetAttribute(k_dots, cudaFuncAttributeMaxDynamicSharedMemorySize, SM_DOTS);

    k_prep<<<dim3(32, 16), dim3(32, 8)>>>(e1, e2);
    k_dots<<<dim3(8, 16), 512, SM_DOTS>>>();
    k_stats<<<dim3(MM, 2), 128>>>(out);
}